// round 3
// baseline (speedup 1.0000x reference)
#include <cuda_runtime.h>
#include <math.h>

#define NI 32     // images
#define NB 128    // captions
#define RR 128    // reduced channels
#define LL 1024   // latent
#define TT 64     // initial time

typedef unsigned long long u64;

// ---------------- packed f32x2 helpers (sm_103a FFMA2 path) ----------------
__device__ __forceinline__ u64 pk2(float lo, float hi) {
    u64 v; asm("mov.b64 %0, {%1, %2};" : "=l"(v) : "f"(lo), "f"(hi)); return v;
}
__device__ __forceinline__ u64 bc2(float x) { return pk2(x, x); }
__device__ __forceinline__ void up2(u64 v, float& lo, float& hi) {
    asm("mov.b64 {%0, %1}, %2;" : "=f"(lo), "=f"(hi) : "l"(v));
}
__device__ __forceinline__ u64 fma2(u64 a, u64 b, u64 c) {
    u64 d; asm("fma.rn.f32x2 %0, %1, %2, %3;" : "=l"(d) : "l"(a), "l"(b), "l"(c)); return d;
}

// ---------------- device scratch (static globals; no allocation) ----------------
__device__ float  g_cap_red[NB*RR*TT];                 // [b][o][64]
__device__ float  g_img_global[NI*LL];
__device__ float  g_inorm[NI];
__device__ float  g_img_vec[NI*RR];
__device__ float  g_kern[NI*2*128*128];                // [(i*2+j)][cik][o]
__device__ float  g_caWT[2*128*128];                   // [j][cik][o]
__device__ float  g_c1WT[2*256*128];                   // [j][ch][o]
__device__ float  g_WfcT[128*1024];                    // [c][l]
__device__ double g_stats[2*NI*512];                   // per-j per-image per-channel sum/sumsq
__device__ float  g_h[(size_t)NI*NB*256*64];           // conv outputs (px|ax)
__device__ float  g_x[(size_t)NI*NB*128*64];           // block activations
__device__ float  g_y[(size_t)NI*NB*1024];             // max-pooled pre-norm

// ---------------- stage 1: image prep (mean, norm, hypernet base) ----------------
__global__ __launch_bounds__(256) void k_img_prep(const float* __restrict__ img_embed,
                                                  const float* __restrict__ W_ri,
                                                  const float* __restrict__ b_ri) {
    __shared__ float gsh[LL];
    __shared__ float red[256];
    int i = blockIdx.x, tid = threadIdx.x;
    float ssq = 0.f;
    for (int c = tid; c < LL; c += 256) {
        float s = 0.f;
        #pragma unroll
        for (int t = 0; t < 36; t++) s += img_embed[((size_t)i*36 + t)*LL + c];
        s *= (1.0f/36.0f);
        gsh[c] = s;
        g_img_global[i*LL + c] = s;
        ssq += s*s;
    }
    red[tid] = ssq; __syncthreads();
    for (int s = 128; s > 0; s >>= 1) { if (tid < s) red[tid] += red[tid+s]; __syncthreads(); }
    if (tid == 0) g_inorm[i] = sqrtf(red[0]);
    if (tid < RR) {
        int o = tid;
        float acc = b_ri[o];
        const float* w = W_ri + (size_t)o * LL;
        for (int c = 0; c < LL; c++) acc = fmaf(w[c], gsh[c], acc);
        g_img_vec[i*RR + o] = acc;
    }
}

// ---------------- stage 2: hypernet kernel generation + weight BN (+ stats zero) ----
__global__ __launch_bounds__(256) void k_gen(const float* __restrict__ mk_W,
                                             const float* __restrict__ mk_b,
                                             const float* __restrict__ wn_g,
                                             const float* __restrict__ wn_b) {
    extern __shared__ float sm[];
    float* base = sm;          // 128
    float* kraw = sm + 128;    // 16384
    int i = blockIdx.x >> 1, j = blockIdx.x & 1, tid = threadIdx.x;
    for (int z = blockIdx.x*256 + tid; z < 2*NI*512; z += 64*256) g_stats[z] = 0.0;
    if (tid < RR) base[tid] = g_img_vec[i*RR + tid];
    __syncthreads();
    for (int f = tid; f < 16384; f += 256) {
        float acc = mk_b[j*16384 + f];
        const float* w = mk_W + ((size_t)j*16384 + f)*128;
        #pragma unroll 4
        for (int c = 0; c < 128; c++) acc = fmaf(w[c], base[c], acc);
        kraw[f] = acc;
    }
    __syncthreads();
    if (tid < RR) {
        int o = tid;
        const float* kr = kraw + o*128;
        float s = 0.f, s2 = 0.f;
        for (int c = 0; c < 128; c++) { float v = kr[c]; s += v; s2 += v*v; }
        float m   = s * (1.f/128.f);
        float var = s2 * (1.f/128.f) - m*m;
        float a   = wn_g[j*RR+o] * rsqrtf(var + 1e-5f);
        float bb  = wn_b[j*RR+o] - a*m;
        float* dst = g_kern + ((size_t)(i*2+j))*16384;    // [cik][o]
        for (int cik = 0; cik < 128; cik++) dst[cik*128 + o] = fmaf(a, kr[cik], bb);
    }
}

// ---------------- stage 3: caption reduction + weight transposes ----------------
__global__ __launch_bounds__(256) void k_cap_red(const float* __restrict__ cap_embed,
                                                 const float* __restrict__ W_rt,
                                                 const float* __restrict__ b_rt,
                                                 const float* __restrict__ W_fc,
                                                 const float* __restrict__ c1_W,
                                                 const float* __restrict__ ca_W) {
    extern __shared__ float sm[];
    float* ce = sm;                      // [c 300][t 64]
    int b = blockIdx.x, tid = threadIdx.x;
    {
        const int N1 = 128*1024, N2 = 2*256*128, N3 = 2*128*128;
        for (int t = b*256 + tid; t < N1+N2+N3; t += NB*256) {
            if (t < N1) {
                int c = t >> 10, l = t & 1023;
                g_WfcT[t] = W_fc[l*128 + c];
            } else if (t < N1+N2) {
                int u = t - N1;
                int j = u >> 15; int v = u & 32767; int ch = v >> 7, o = v & 127;
                g_c1WT[u] = c1_W[(j*128 + o)*256 + ch];
            } else {
                int u = t - N1 - N2;
                int j = u >> 14; int v = u & 16383; int cik = v >> 7, o = v & 127;
                g_caWT[u] = ca_W[(j*128 + o)*128 + cik];
            }
        }
    }
    for (int idx = tid; idx < 300*TT; idx += 256) {
        int c = idx >> 6, t = idx & 63;
        ce[idx] = cap_embed[(size_t)b*TT*300 + t*300 + c];
    }
    __syncthreads();
    for (int q = tid; q < RR*16; q += 256) {
        int o = q >> 4, tq = (q & 15) * 4;
        float a0 = 0.f, a1 = 0.f, a2 = 0.f, a3 = 0.f;
        const float* w = W_rt + o*300;
        for (int c = 0; c < 300; c++) {
            float wv = w[c];
            float4 x4 = *(const float4*)(ce + c*TT + tq);
            a0 = fmaf(wv, x4.x, a0); a1 = fmaf(wv, x4.y, a1);
            a2 = fmaf(wv, x4.z, a2); a3 = fmaf(wv, x4.w, a3);
        }
        float bo = b_rt[o];
        float* dst = g_cap_red + ((size_t)b*RR + o)*TT + tq;
        dst[0] = a0 + bo; dst[1] = a1 + bo; dst[2] = a2 + bo; dst[3] = a3 + bo;
    }
}

// ---------------- stage 4: grouped convs, 512 threads (16 warps/SM) ----------------
template<int TOUT>
__global__ __launch_bounds__(512) void k_conv(int j) {
    extern __shared__ float sm[];
    float* xs  = sm;                    // [128][64]
    float* wpx = sm + 8192;             // [cik][o]
    float* wax = sm + 8192 + 16384;     // [cik][o]
    int b = blockIdx.x, i = blockIdx.y, tid = threadIdx.x;
    const float* xin = (j == 0) ? (g_cap_red + (size_t)b*8192)
                                : (g_x + ((size_t)i*NB + b)*8192);
    for (int idx = tid; idx < 8192; idx += 512) xs[idx] = xin[idx];
    const float* kp = g_kern + (size_t)(i*2 + j)*16384;
    const float* ka = g_caWT + (size_t)j*16384;
    for (int idx = tid; idx < 16384; idx += 512) { wpx[idx] = kp[idx]; wax[idx] = ka[idx]; }
    __syncthreads();

    int opair = tid & 63, th = tid >> 6;       // 64 o-pairs x 8 t-chunks
    const float* xg = xs + (opair >> 5) * 4096;
    const int wo = opair * 2;
    const int t0 = th * 8;

    u64 accP[8], accA[8];
    #pragma unroll
    for (int t = 0; t < 8; t++) { accP[t] = 0ull; accA[t] = 0ull; }
    #pragma unroll 2
    for (int ci = 0; ci < 64; ci++) {
        const float* xr = xg + ci*64 + t0;
        float4 xlo = *(const float4*)xr;
        float4 xhi = *(const float4*)(xr + 4);
        float x8v = xr[8];   // may read 1 past row for last chunk; result discarded
        u64 xx[9];
        xx[0]=bc2(xlo.x); xx[1]=bc2(xlo.y); xx[2]=bc2(xlo.z); xx[3]=bc2(xlo.w);
        xx[4]=bc2(xhi.x); xx[5]=bc2(xhi.y); xx[6]=bc2(xhi.z); xx[7]=bc2(xhi.w);
        xx[8]=bc2(x8v);
        u64 wp0 = *(const u64*)(wpx + (ci*2  )*128 + wo);
        u64 wp1 = *(const u64*)(wpx + (ci*2+1)*128 + wo);
        u64 wa0 = *(const u64*)(wax + (ci*2  )*128 + wo);
        u64 wa1 = *(const u64*)(wax + (ci*2+1)*128 + wo);
        #pragma unroll
        for (int t = 0; t < 8; t++) {
            accP[t] = fma2(wp0, xx[t],   accP[t]);
            accP[t] = fma2(wp1, xx[t+1], accP[t]);
            accA[t] = fma2(wa0, xx[t],   accA[t]);
            accA[t] = fma2(wa1, xx[t+1], accA[t]);
        }
    }
    float sp0=0.f, sp0q=0.f, sp1=0.f, sp1q=0.f;
    float sa0=0.f, sa0q=0.f, sa1=0.f, sa1q=0.f;
    float* hp = g_h + ((size_t)(i*NB + b))*16384;   // [256 ch][64 t]
    #pragma unroll
    for (int t = 0; t < 8; t++) {
        int tg = t0 + t;
        if (tg < TOUT) {
            float p0, p1, a0, a1;
            up2(accP[t], p0, p1);
            up2(accA[t], a0, a1);
            hp[(wo  )*64 + tg] = p0;
            hp[(wo+1)*64 + tg] = p1;
            hp[(128+wo  )*64 + tg] = a0;
            hp[(128+wo+1)*64 + tg] = a1;
            sp0 += p0; sp0q += p0*p0; sp1 += p1; sp1q += p1*p1;
            sa0 += a0; sa0q += a0*a0; sa1 += a1; sa1q += a1*a1;
        }
    }
    double* st = g_stats + ((size_t)j*NI + i)*512;
    atomicAdd(st + (wo      )*2    , (double)sp0);
    atomicAdd(st + (wo      )*2 + 1, (double)sp0q);
    atomicAdd(st + (wo+1    )*2    , (double)sp1);
    atomicAdd(st + (wo+1    )*2 + 1, (double)sp1q);
    atomicAdd(st + (128+wo  )*2    , (double)sa0);
    atomicAdd(st + (128+wo  )*2 + 1, (double)sa0q);
    atomicAdd(st + (128+wo+1)*2    , (double)sa1);
    atomicAdd(st + (128+wo+1)*2 + 1, (double)sa1q);
}

// ---------------- stage 5: BN+ReLU + 1x1 mixing conv (c1), 512 threads ----------
template<int TOUT>
__global__ __launch_bounds__(512) void k_c1(const float* __restrict__ bn_g,
                                            const float* __restrict__ bn_b,
                                            const float* __restrict__ c1_b, int j) {
    extern __shared__ float sm[];
    float* hs = sm;                       // [256][64]
    float* ws = sm + 16384;               // [ch][o]
    float* aa = sm + 49152;               // 256
    float* bb = sm + 49408;               // 256
    int b = blockIdx.x, i = blockIdx.y, tid = threadIdx.x;
    if (tid < 256) {
        double s  = g_stats[((size_t)j*NI + i)*512 + tid*2];
        double s2 = g_stats[((size_t)j*NI + i)*512 + tid*2 + 1];
        double n  = (double)(NB*TOUT);
        float m   = (float)(s / n);
        float var = (float)(s2 / n) - m*m;
        float a   = bn_g[j*256 + tid] * rsqrtf(var + 1e-5f);
        aa[tid] = a;
        bb[tid] = bn_b[j*256 + tid] - a*m;
    }
    __syncthreads();
    const float* hsrc = g_h + (size_t)(i*NB + b)*16384;
    for (int idx = tid; idx < 16384; idx += 512) {
        int ch = idx >> 6, t = idx & 63;
        float v = fmaf(aa[ch], hsrc[idx], bb[ch]);
        hs[idx] = (t < TOUT) ? fmaxf(v, 0.f) : 0.f;
    }
    const float* wsrc = g_c1WT + j*32768;
    for (int idx = tid; idx < 32768; idx += 512) ws[idx] = wsrc[idx];
    __syncthreads();

    // 32 lanes (2 o-pairs each) x 16 t-slots (4 t each)
    int lane = tid & 31, ts = tid >> 5;
    int t0 = ts * 4;
    u64 acc0[4], acc1[4];
    #pragma unroll
    for (int t = 0; t < 4; t++) { acc0[t] = 0ull; acc1[t] = 0ull; }
    #pragma unroll 2
    for (int ch = 0; ch < 256; ch++) {
        u64 w0 = *(const u64*)(ws + ch*128 + 2*lane);
        u64 w1 = *(const u64*)(ws + ch*128 + 64 + 2*lane);
        float4 xa = *(const float4*)(hs + ch*64 + t0);
        u64 xx[4];
        xx[0]=bc2(xa.x); xx[1]=bc2(xa.y); xx[2]=bc2(xa.z); xx[3]=bc2(xa.w);
        #pragma unroll
        for (int t = 0; t < 4; t++) {
            acc0[t] = fma2(w0, xx[t], acc0[t]);
            acc1[t] = fma2(w1, xx[t], acc1[t]);
        }
    }
    float* xout = g_x + (size_t)(i*NB + b)*8192;
    int oA = 2*lane, oB = 64 + 2*lane;
    float cbA0 = c1_b[j*128+oA],   cbA1 = c1_b[j*128+oA+1];
    float cbB0 = c1_b[j*128+oB],   cbB1 = c1_b[j*128+oB+1];
    #pragma unroll
    for (int t = 0; t < 4; t++) {
        int tg = t0 + t;
        if (tg < TOUT) {
            float lo, hi;
            up2(acc0[t], lo, hi);
            xout[oA*64 + tg] = lo + cbA0; xout[(oA+1)*64 + tg] = hi + cbA1;
            up2(acc1[t], lo, hi);
            xout[oB*64 + tg] = lo + cbB0; xout[(oB+1)*64 + tg] = hi + cbB1;
        }
    }
}

// ---------------- stage 6: W_fc GEMM + max-over-time, 512 threads / 2 captions ----
__global__ __launch_bounds__(512) void k_fc_max(const float* __restrict__ b_fc) {
    extern __shared__ float sm[];
    float* wts = sm;                   // [c 128][l 128]
    float* xs  = sm + 16384;           // 2 x [c 128][t 64]
    float* red = sm + 32768;           // 2 x [warp 8][l 128]
    int lt = blockIdx.x, bp = blockIdx.y, i = blockIdx.z, tid = threadIdx.x;
    int half = tid >> 8, t8 = tid & 255;
    int b = bp*2 + half;
    for (int idx = tid; idx < 16384; idx += 512) {
        int c = idx >> 7, l = idx & 127;
        wts[idx] = g_WfcT[c*1024 + lt*128 + l];
    }
    float* xsh = xs + half*8192;
    float* redh = red + half*1024;
    const float* xin = g_x + (size_t)(i*NB + b)*8192;
    for (int idx = t8; idx < 8192; idx += 256) {
        int t = idx & 63;
        xsh[idx] = (t < 62) ? xin[idx] : 0.f;
    }
    __syncthreads();

    int lane = t8 & 31, wp = t8 >> 5;
    int t0 = wp * 8;
    u64 acc0[8], acc1[8];
    #pragma unroll
    for (int t = 0; t < 8; t++) { acc0[t] = 0ull; acc1[t] = 0ull; }
    #pragma unroll 2
    for (int c = 0; c < 128; c++) {
        u64 w0 = *(const u64*)(wts + c*128 + 2*lane);
        u64 w1 = *(const u64*)(wts + c*128 + 64 + 2*lane);
        float4 xa = *(const float4*)(xsh + c*64 + t0);
        float4 xb = *(const float4*)(xsh + c*64 + t0 + 4);
        u64 xx[8];
        xx[0]=bc2(xa.x); xx[1]=bc2(xa.y); xx[2]=bc2(xa.z); xx[3]=bc2(xa.w);
        xx[4]=bc2(xb.x); xx[5]=bc2(xb.y); xx[6]=bc2(xb.z); xx[7]=bc2(xb.w);
        #pragma unroll
        for (int t = 0; t < 8; t++) {
            acc0[t] = fma2(w0, xx[t], acc0[t]);
            acc1[t] = fma2(w1, xx[t], acc1[t]);
        }
    }
    float m0 = -1e30f, m1 = -1e30f, m2 = -1e30f, m3 = -1e30f;
    #pragma unroll
    for (int t = 0; t < 8; t++) {
        if (t0 + t < 62) {
            float lo, hi;
            up2(acc0[t], lo, hi); m0 = fmaxf(m0, lo); m1 = fmaxf(m1, hi);
            up2(acc1[t], lo, hi); m2 = fmaxf(m2, lo); m3 = fmaxf(m3, hi);
        }
    }
    redh[wp*128 + 2*lane    ] = m0;
    redh[wp*128 + 2*lane + 1] = m1;
    redh[wp*128 + 64 + 2*lane    ] = m2;
    redh[wp*128 + 64 + 2*lane + 1] = m3;
    __syncthreads();
    if (t8 < 128) {
        float y = redh[t8];
        #pragma unroll
        for (int w2 = 1; w2 < 8; w2++) y = fmaxf(y, redh[w2*128 + t8]);
        y += b_fc[lt*128 + t8];
        g_y[(size_t)(i*NB + b)*1024 + lt*128 + t8] = y;
    }
}

// ---------------- stage 7: normalize + dot ----------------
__global__ __launch_bounds__(256) void k_final(float* __restrict__ out) {
    __shared__ float r1[256], r2[256];
    int b = blockIdx.x, i = blockIdx.y, tid = threadIdx.x;
    const float* y = g_y + (size_t)(i*NB + b)*1024;
    const float* g = g_img_global + i*LL;
    float d = 0.f, ss = 0.f;
    for (int l = tid; l < 1024; l += 256) { float yv = y[l]; d = fmaf(yv, g[l], d); ss = fmaf(yv, yv, ss); }
    r1[tid] = d; r2[tid] = ss; __syncthreads();
    for (int s = 128; s > 0; s >>= 1) {
        if (tid < s) { r1[tid] += r1[tid+s]; r2[tid] += r2[tid+s]; }
        __syncthreads();
    }
    if (tid == 0) out[i*NB + b] = r1[0] / (sqrtf(r2[0]) * g_inorm[i]);
}

// ---------------- launch ----------------
extern "C" void kernel_launch(void* const* d_in, const int* in_sizes, int n_in,
                              void* d_out, int out_size) {
    (void)in_sizes; (void)n_in; (void)out_size;
    const float* img_embed = (const float*)d_in[0];
    const float* cap_embed = (const float*)d_in[1];
    const float* W_ri = (const float*)d_in[2];
    const float* b_ri = (const float*)d_in[3];
    const float* W_rt = (const float*)d_in[4];
    const float* b_rt = (const float*)d_in[5];
    const float* mk_W = (const float*)d_in[6];
    const float* mk_b = (const float*)d_in[7];
    // d_in[8]=mbias_W, d_in[9]=mbias_b, d_in[13]=ca_b: exactly cancelled by training-mode BN
    const float* wn_g = (const float*)d_in[10];
    const float* wn_b = (const float*)d_in[11];
    const float* ca_W = (const float*)d_in[12];
    const float* bn_g = (const float*)d_in[14];
    const float* bn_b = (const float*)d_in[15];
    const float* c1_W = (const float*)d_in[16];
    const float* c1_b = (const float*)d_in[17];
    const float* W_fc = (const float*)d_in[18];
    const float* b_fc = (const float*)d_in[19];
    float* out = (float*)d_out;

    const int CAP_SMEM  = 300*64*4;
    const int GEN_SMEM  = (128 + 16384)*4;
    const int CONV_SMEM = (8192 + 16384 + 16384)*4;
    const int C1_SMEM   = (16384 + 32768 + 512)*4;
    const int FC_SMEM   = (16384 + 16384 + 2048)*4;
    cudaFuncSetAttribute((const void*)k_cap_red,  cudaFuncAttributeMaxDynamicSharedMemorySize, CAP_SMEM);
    cudaFuncSetAttribute((const void*)k_gen,      cudaFuncAttributeMaxDynamicSharedMemorySize, GEN_SMEM);
    cudaFuncSetAttribute((const void*)k_conv<63>, cudaFuncAttributeMaxDynamicSharedMemorySize, CONV_SMEM);
    cudaFuncSetAttribute((const void*)k_conv<62>, cudaFuncAttributeMaxDynamicSharedMemorySize, CONV_SMEM);
    cudaFuncSetAttribute((const void*)k_c1<63>,   cudaFuncAttributeMaxDynamicSharedMemorySize, C1_SMEM);
    cudaFuncSetAttribute((const void*)k_c1<62>,   cudaFuncAttributeMaxDynamicSharedMemorySize, C1_SMEM);
    cudaFuncSetAttribute((const void*)k_fc_max,   cudaFuncAttributeMaxDynamicSharedMemorySize, FC_SMEM);

    k_img_prep<<<NI, 256>>>(img_embed, W_ri, b_ri);
    k_gen<<<NI*2, 256, GEN_SMEM>>>(mk_W, mk_b, wn_g, wn_b);
    k_cap_red<<<NB, 256, CAP_SMEM>>>(cap_embed, W_rt, b_rt, W_fc, c1_W, ca_W);

    // block j = 0 (T 64 -> 63)
    k_conv<63><<<dim3(NB, NI), 512, CONV_SMEM>>>(0);
    k_c1<63><<<dim3(NB, NI), 512, C1_SMEM>>>(bn_g, bn_b, c1_b, 0);

    // block j = 1 (T 63 -> 62)
    k_conv<62><<<dim3(NB, NI), 512, CONV_SMEM>>>(1);
    k_c1<62><<<dim3(NB, NI), 512, C1_SMEM>>>(bn_g, bn_b, c1_b, 1);

    // W_fc + max over time, then normalize + dot
    k_fc_max<<<dim3(8, NB/2, NI), 512, FC_SMEM>>>(b_fc);
    k_final<<<dim3(NB, NI), 256>>>(out);
}

// round 5
// speedup vs baseline: 1.1259x; 1.1259x over previous
#include <cuda_runtime.h>
#include <math.h>

#define NI 32     // images
#define NB 128    // captions
#define RR 128    // reduced channels
#define LL 1024   // latent
#define TT 64     // initial time

typedef unsigned long long u64;

// ---------------- packed f32x2 helpers (sm_103a FFMA2 path) ----------------
__device__ __forceinline__ u64 pk2(float lo, float hi) {
    u64 v; asm("mov.b64 %0, {%1, %2};" : "=l"(v) : "f"(lo), "f"(hi)); return v;
}
__device__ __forceinline__ u64 bc2(float x) { return pk2(x, x); }
__device__ __forceinline__ void up2(u64 v, float& lo, float& hi) {
    asm("mov.b64 {%0, %1}, %2;" : "=f"(lo), "=f"(hi) : "l"(v));
}
__device__ __forceinline__ u64 fma2(u64 a, u64 b, u64 c) {
    u64 d; asm("fma.rn.f32x2 %0, %1, %2, %3;" : "=l"(d) : "l"(a), "l"(b), "l"(c)); return d;
}

// ---------------- device scratch (static globals; no allocation) ----------------
__device__ float  g_cap_red[NB*RR*TT];                 // [b][o][64]
__device__ float  g_img_global[NI*LL];
__device__ float  g_inorm[NI];
__device__ float  g_img_vec[NI*RR];
__device__ float  g_kern[NI*2*128*128];                // [(i*2+j)][cik][o]
__device__ float  g_caWT[2*128*128];                   // [j][cik][o]
__device__ float  g_c1WT[2*256*128];                   // [j][ch][o]
__device__ float  g_WfcT[128*1024];                    // [c][l]
__device__ double g_stats[2*NI*512];                   // per-j per-image per-channel sum/sumsq
__device__ float  g_h[(size_t)NI*NB*256*64];           // conv outputs (px|ax)
__device__ float  g_x[(size_t)NI*NB*128*64];           // block activations
__device__ float  g_y[(size_t)NI*NB*1024];             // max-pooled pre-norm

// ---------------- stage 1: image prep (mean, norm, hypernet base) ----------------
__global__ __launch_bounds__(256) void k_img_prep(const float* __restrict__ img_embed,
                                                  const float* __restrict__ W_ri,
                                                  const float* __restrict__ b_ri) {
    __shared__ float gsh[LL];
    __shared__ float red[256];
    int i = blockIdx.x, tid = threadIdx.x;
    float ssq = 0.f;
    for (int c = tid; c < LL; c += 256) {
        float s = 0.f;
        #pragma unroll
        for (int t = 0; t < 36; t++) s += img_embed[((size_t)i*36 + t)*LL + c];
        s *= (1.0f/36.0f);
        gsh[c] = s;
        g_img_global[i*LL + c] = s;
        ssq += s*s;
    }
    red[tid] = ssq; __syncthreads();
    for (int s = 128; s > 0; s >>= 1) { if (tid < s) red[tid] += red[tid+s]; __syncthreads(); }
    if (tid == 0) g_inorm[i] = sqrtf(red[0]);
    if (tid < RR) {
        int o = tid;
        float acc = b_ri[o];
        const float* w = W_ri + (size_t)o * LL;
        for (int c = 0; c < LL; c++) acc = fmaf(w[c], gsh[c], acc);
        g_img_vec[i*RR + o] = acc;
    }
}

// ---------------- stage 2: hypernet kernel generation + weight BN (+ stats zero) ----
__global__ __launch_bounds__(256) void k_gen(const float* __restrict__ mk_W,
                                             const float* __restrict__ mk_b,
                                             const float* __restrict__ wn_g,
                                             const float* __restrict__ wn_b) {
    extern __shared__ float sm[];
    float* base = sm;          // 128
    float* kraw = sm + 128;    // 16384
    int i = blockIdx.x >> 1, j = blockIdx.x & 1, tid = threadIdx.x;
    for (int z = blockIdx.x*256 + tid; z < 2*NI*512; z += 64*256) g_stats[z] = 0.0;
    if (tid < RR) base[tid] = g_img_vec[i*RR + tid];
    __syncthreads();
    for (int f = tid; f < 16384; f += 256) {
        float acc = mk_b[j*16384 + f];
        const float* w = mk_W + ((size_t)j*16384 + f)*128;
        #pragma unroll 4
        for (int c = 0; c < 128; c++) acc = fmaf(w[c], base[c], acc);
        kraw[f] = acc;
    }
    __syncthreads();
    if (tid < RR) {
        int o = tid;
        const float* kr = kraw + o*128;
        float s = 0.f, s2 = 0.f;
        for (int c = 0; c < 128; c++) { float v = kr[c]; s += v; s2 += v*v; }
        float m   = s * (1.f/128.f);
        float var = s2 * (1.f/128.f) - m*m;
        float a   = wn_g[j*RR+o] * rsqrtf(var + 1e-5f);
        float bb  = wn_b[j*RR+o] - a*m;
        float* dst = g_kern + ((size_t)(i*2+j))*16384;    // [cik][o]
        for (int cik = 0; cik < 128; cik++) dst[cik*128 + o] = fmaf(a, kr[cik], bb);
    }
}

// ---------------- stage 3: caption reduction + weight transposes ----------------
__global__ __launch_bounds__(256) void k_cap_red(const float* __restrict__ cap_embed,
                                                 const float* __restrict__ W_rt,
                                                 const float* __restrict__ b_rt,
                                                 const float* __restrict__ W_fc,
                                                 const float* __restrict__ c1_W,
                                                 const float* __restrict__ ca_W) {
    extern __shared__ float sm[];
    float* ce = sm;                      // [c 300][t 64]
    int b = blockIdx.x, tid = threadIdx.x;
    {
        const int N1 = 128*1024, N2 = 2*256*128, N3 = 2*128*128;
        for (int t = b*256 + tid; t < N1+N2+N3; t += NB*256) {
            if (t < N1) {
                int c = t >> 10, l = t & 1023;
                g_WfcT[t] = W_fc[l*128 + c];
            } else if (t < N1+N2) {
                int u = t - N1;
                int j = u >> 15; int v = u & 32767; int ch = v >> 7, o = v & 127;
                g_c1WT[u] = c1_W[(j*128 + o)*256 + ch];
            } else {
                int u = t - N1 - N2;
                int j = u >> 14; int v = u & 16383; int cik = v >> 7, o = v & 127;
                g_caWT[u] = ca_W[(j*128 + o)*128 + cik];
            }
        }
    }
    for (int idx = tid; idx < 300*TT; idx += 256) {
        int c = idx >> 6, t = idx & 63;
        ce[idx] = cap_embed[(size_t)b*TT*300 + t*300 + c];
    }
    __syncthreads();
    for (int q = tid; q < RR*16; q += 256) {
        int o = q >> 4, tq = (q & 15) * 4;
        float a0 = 0.f, a1 = 0.f, a2 = 0.f, a3 = 0.f;
        const float* w = W_rt + o*300;
        for (int c = 0; c < 300; c++) {
            float wv = w[c];
            float4 x4 = *(const float4*)(ce + c*TT + tq);
            a0 = fmaf(wv, x4.x, a0); a1 = fmaf(wv, x4.y, a1);
            a2 = fmaf(wv, x4.z, a2); a3 = fmaf(wv, x4.w, a3);
        }
        float bo = b_rt[o];
        float* dst = g_cap_red + ((size_t)b*RR + o)*TT + tq;
        dst[0] = a0 + bo; dst[1] = a1 + bo; dst[2] = a2 + bo; dst[3] = a3 + bo;
    }
}

// ---------------- stage 4: grouped convs + BN stats, 4 captions per CTA ----------
template<int TOUT>
__global__ __launch_bounds__(256) void k_conv(int j) {
    extern __shared__ float sm[];
    float* xs  = sm;                    // [128][64]
    float* wpx = sm + 8192;             // [cik][o]
    float* wax = sm + 8192 + 16384;     // [cik][o]
    int bq = blockIdx.x, i = blockIdx.y, tid = threadIdx.x;
    const float* kp = g_kern + (size_t)(i*2 + j)*16384;
    const float* ka = g_caWT + (size_t)j*16384;
    for (int idx = tid; idx < 16384; idx += 256) { wpx[idx] = kp[idx]; wax[idx] = ka[idx]; }

    int opair = tid & 63, th = tid >> 6;       // 64 o-pairs x 4 t-slots
    const float* xg = xs + (opair >> 5) * 4096;
    const int wo = opair * 2;
    float sp0=0.f, sp0q=0.f, sp1=0.f, sp1q=0.f;
    float sa0=0.f, sa0q=0.f, sa1=0.f, sa1q=0.f;

    for (int bs = 0; bs < 4; bs++) {
        int b = bq*4 + bs;
        const float* xin = (j == 0) ? (g_cap_red + (size_t)b*8192)
                                    : (g_x + ((size_t)i*NB + b)*8192);
        __syncthreads();   // xs reuse: previous iteration fully consumed
        for (int idx = tid; idx < 8192; idx += 256) xs[idx] = xin[idx];
        __syncthreads();

        for (int chunk = th; chunk < 8; chunk += 4) {
            int t0 = chunk * 8;
            u64 accP[8], accA[8];
            #pragma unroll
            for (int t = 0; t < 8; t++) { accP[t] = 0ull; accA[t] = 0ull; }
            #pragma unroll 2
            for (int ci = 0; ci < 64; ci++) {
                const float* xr = xg + ci*64 + t0;
                float4 xlo = *(const float4*)xr;
                float4 xhi = *(const float4*)(xr + 4);
                float x8v = xr[8];   // may read 1 past row for last chunk; discarded
                u64 xx[9];
                xx[0]=bc2(xlo.x); xx[1]=bc2(xlo.y); xx[2]=bc2(xlo.z); xx[3]=bc2(xlo.w);
                xx[4]=bc2(xhi.x); xx[5]=bc2(xhi.y); xx[6]=bc2(xhi.z); xx[7]=bc2(xhi.w);
                xx[8]=bc2(x8v);
                u64 wp0 = *(const u64*)(wpx + (ci*2  )*128 + wo);
                u64 wp1 = *(const u64*)(wpx + (ci*2+1)*128 + wo);
                u64 wa0 = *(const u64*)(wax + (ci*2  )*128 + wo);
                u64 wa1 = *(const u64*)(wax + (ci*2+1)*128 + wo);
                #pragma unroll
                for (int t = 0; t < 8; t++) {
                    accP[t] = fma2(wp0, xx[t],   accP[t]);
                    accP[t] = fma2(wp1, xx[t+1], accP[t]);
                    accA[t] = fma2(wa0, xx[t],   accA[t]);
                    accA[t] = fma2(wa1, xx[t+1], accA[t]);
                }
            }
            float* hp = g_h + ((size_t)(i*NB + b))*16384;   // [256 ch][64 t]
            #pragma unroll
            for (int t = 0; t < 8; t++) {
                int tg = t0 + t;
                if (tg < TOUT) {
                    float p0, p1, a0, a1;
                    up2(accP[t], p0, p1);
                    up2(accA[t], a0, a1);
                    hp[(wo  )*64 + tg] = p0;
                    hp[(wo+1)*64 + tg] = p1;
                    hp[(128+wo  )*64 + tg] = a0;
                    hp[(128+wo+1)*64 + tg] = a1;
                    sp0 += p0; sp0q += p0*p0; sp1 += p1; sp1q += p1*p1;
                    sa0 += a0; sa0q += a0*a0; sa1 += a1; sa1q += a1*a1;
                }
            }
        }
    }
    double* st = g_stats + ((size_t)j*NI + i)*512;
    atomicAdd(st + (wo      )*2    , (double)sp0);
    atomicAdd(st + (wo      )*2 + 1, (double)sp0q);
    atomicAdd(st + (wo+1    )*2    , (double)sp1);
    atomicAdd(st + (wo+1    )*2 + 1, (double)sp1q);
    atomicAdd(st + (128+wo  )*2    , (double)sa0);
    atomicAdd(st + (128+wo  )*2 + 1, (double)sa0q);
    atomicAdd(st + (128+wo+1)*2    , (double)sa1);
    atomicAdd(st + (128+wo+1)*2 + 1, (double)sa1q);
}

// ---------------- stage 5: BN+ReLU + 1x1 mixing conv (c1), 4 captions per CTA ------
template<int TOUT>
__global__ __launch_bounds__(256) void k_c1(const float* __restrict__ bn_g,
                                            const float* __restrict__ bn_b,
                                            const float* __restrict__ c1_b, int j) {
    extern __shared__ float sm[];
    float* hs = sm;                       // [256][64]
    float* ws = sm + 16384;               // [ch][o]
    float* aa = sm + 49152;               // 256
    float* bb = sm + 49408;               // 256
    int bq = blockIdx.x, i = blockIdx.y, tid = threadIdx.x;
    {
        double s  = g_stats[((size_t)j*NI + i)*512 + tid*2];
        double s2 = g_stats[((size_t)j*NI + i)*512 + tid*2 + 1];
        double n  = (double)(NB*TOUT);
        float m   = (float)(s / n);
        float var = (float)(s2 / n) - m*m;
        float a   = bn_g[j*256 + tid] * rsqrtf(var + 1e-5f);
        aa[tid] = a;
        bb[tid] = bn_b[j*256 + tid] - a*m;
    }
    const float* wsrc = g_c1WT + j*32768;
    for (int idx = tid; idx < 32768; idx += 256) ws[idx] = wsrc[idx];

    int lane = tid & 31, wp = tid >> 5;
    int t0 = wp * 8;
    int oA = 2*lane, oB = 64 + 2*lane;
    float cbA0 = c1_b[j*128+oA],   cbA1 = c1_b[j*128+oA+1];
    float cbB0 = c1_b[j*128+oB],   cbB1 = c1_b[j*128+oB+1];

    for (int bs = 0; bs < 4; bs++) {
        int b = bq*4 + bs;
        const float* hsrc = g_h + (size_t)(i*NB + b)*16384;
        __syncthreads();   // hs reuse
        for (int idx = tid; idx < 16384; idx += 256) {
            int ch = idx >> 6, t = idx & 63;
            float v = fmaf(aa[ch], hsrc[idx], bb[ch]);
            hs[idx] = (t < TOUT) ? fmaxf(v, 0.f) : 0.f;
        }
        __syncthreads();

        u64 acc0[8], acc1[8];
        #pragma unroll
        for (int t = 0; t < 8; t++) { acc0[t] = 0ull; acc1[t] = 0ull; }
        #pragma unroll 2
        for (int ch = 0; ch < 256; ch++) {
            u64 w0 = *(const u64*)(ws + ch*128 + 2*lane);
            u64 w1 = *(const u64*)(ws + ch*128 + 64 + 2*lane);
            float4 xa = *(const float4*)(hs + ch*64 + t0);
            float4 xb = *(const float4*)(hs + ch*64 + t0 + 4);
            u64 xx[8];
            xx[0]=bc2(xa.x); xx[1]=bc2(xa.y); xx[2]=bc2(xa.z); xx[3]=bc2(xa.w);
            xx[4]=bc2(xb.x); xx[5]=bc2(xb.y); xx[6]=bc2(xb.z); xx[7]=bc2(xb.w);
            #pragma unroll
            for (int t = 0; t < 8; t++) {
                acc0[t] = fma2(w0, xx[t], acc0[t]);
                acc1[t] = fma2(w1, xx[t], acc1[t]);
            }
        }
        float* xout = g_x + (size_t)(i*NB + b)*8192;
        #pragma unroll
        for (int t = 0; t < 8; t++) {
            int tg = t0 + t;
            if (tg < TOUT) {
                float lo, hi;
                up2(acc0[t], lo, hi);
                xout[oA*64 + tg] = lo + cbA0; xout[(oA+1)*64 + tg] = hi + cbA1;
                up2(acc1[t], lo, hi);
                xout[oB*64 + tg] = lo + cbB0; xout[(oB+1)*64 + tg] = hi + cbB1;
            }
        }
    }
}

// ---------------- stage 6: W_fc GEMM + max-over-time, 16 captions per CTA ----------
__global__ __launch_bounds__(256) void k_fc_max(const float* __restrict__ b_fc) {
    extern __shared__ float sm[];
    float* wts = sm;                  // [c 128][l 128]  64KB, loaded once
    float* xs  = sm + 16384;          // [c 128][t 64]   32KB, per caption
    float* red = sm + 16384 + 8192;   // [warp 8][l 128]  4KB
    int lt = blockIdx.x, bg = blockIdx.y, i = blockIdx.z, tid = threadIdx.x;
    for (int idx = tid; idx < 16384; idx += 256) {
        int c = idx >> 7, l = idx & 127;
        wts[idx] = g_WfcT[c*1024 + lt*128 + l];
    }
    int lane = tid & 31, wp = tid >> 5;
    int t0 = wp * 8;
    float bfc0 = 0.f;
    if (tid < 128) bfc0 = b_fc[lt*128 + tid];

    for (int bs = 0; bs < 16; bs++) {
        int b = bg*16 + bs;
        const float* xin = g_x + (size_t)(i*NB + b)*8192;
        __syncthreads();   // xs + red reuse
        for (int idx = tid; idx < 8192; idx += 256) {
            int t = idx & 63;
            xs[idx] = (t < 62) ? xin[idx] : 0.f;
        }
        __syncthreads();

        u64 acc0[8], acc1[8];
        #pragma unroll
        for (int t = 0; t < 8; t++) { acc0[t] = 0ull; acc1[t] = 0ull; }
        #pragma unroll 2
        for (int c = 0; c < 128; c++) {
            u64 w0 = *(const u64*)(wts + c*128 + 2*lane);
            u64 w1 = *(const u64*)(wts + c*128 + 64 + 2*lane);
            float4 xa = *(const float4*)(xs + c*64 + t0);
            float4 xb = *(const float4*)(xs + c*64 + t0 + 4);
            u64 xx[8];
            xx[0]=bc2(xa.x); xx[1]=bc2(xa.y); xx[2]=bc2(xa.z); xx[3]=bc2(xa.w);
            xx[4]=bc2(xb.x); xx[5]=bc2(xb.y); xx[6]=bc2(xb.z); xx[7]=bc2(xb.w);
            #pragma unroll
            for (int t = 0; t < 8; t++) {
                acc0[t] = fma2(w0, xx[t], acc0[t]);
                acc1[t] = fma2(w1, xx[t], acc1[t]);
            }
        }
        float m0 = -1e30f, m1 = -1e30f, m2 = -1e30f, m3 = -1e30f;
        #pragma unroll
        for (int t = 0; t < 8; t++) {
            if (t0 + t < 62) {
                float lo, hi;
                up2(acc0[t], lo, hi); m0 = fmaxf(m0, lo); m1 = fmaxf(m1, hi);
                up2(acc1[t], lo, hi); m2 = fmaxf(m2, lo); m3 = fmaxf(m3, hi);
            }
        }
        red[wp*128 + 2*lane    ] = m0;
        red[wp*128 + 2*lane + 1] = m1;
        red[wp*128 + 64 + 2*lane    ] = m2;
        red[wp*128 + 64 + 2*lane + 1] = m3;
        __syncthreads();
        if (tid < 128) {
            float y = red[tid];
            #pragma unroll
            for (int w2 = 1; w2 < 8; w2++) y = fmaxf(y, red[w2*128 + tid]);
            y += bfc0;
            g_y[(size_t)(i*NB + b)*1024 + lt*128 + tid] = y;
        }
    }
}

// ---------------- stage 7: normalize + dot ----------------
__global__ __launch_bounds__(256) void k_final(float* __restrict__ out) {
    __shared__ float r1[256], r2[256];
    int b = blockIdx.x, i = blockIdx.y, tid = threadIdx.x;
    const float* y = g_y + (size_t)(i*NB + b)*1024;
    const float* g = g_img_global + i*LL;
    float d = 0.f, ss = 0.f;
    for (int l = tid; l < 1024; l += 256) { float yv = y[l]; d = fmaf(yv, g[l], d); ss = fmaf(yv, yv, ss); }
    r1[tid] = d; r2[tid] = ss; __syncthreads();
    for (int s = 128; s > 0; s >>= 1) {
        if (tid < s) { r1[tid] += r1[tid+s]; r2[tid] += r2[tid+s]; }
        __syncthreads();
    }
    if (tid == 0) out[i*NB + b] = r1[0] / (sqrtf(r2[0]) * g_inorm[i]);
}

// ---------------- launch ----------------
extern "C" void kernel_launch(void* const* d_in, const int* in_sizes, int n_in,
                              void* d_out, int out_size) {
    (void)in_sizes; (void)n_in; (void)out_size;
    const float* img_embed = (const float*)d_in[0];
    const float* cap_embed = (const float*)d_in[1];
    const float* W_ri = (const float*)d_in[2];
    const float* b_ri = (const float*)d_in[3];
    const float* W_rt = (const float*)d_in[4];
    const float* b_rt = (const float*)d_in[5];
    const float* mk_W = (const float*)d_in[6];
    const float* mk_b = (const float*)d_in[7];
    // d_in[8]=mbias_W, d_in[9]=mbias_b, d_in[13]=ca_b: exactly cancelled by training-mode BN
    const float* wn_g = (const float*)d_in[10];
    const float* wn_b = (const float*)d_in[11];
    const float* ca_W = (const float*)d_in[12];
    const float* bn_g = (const float*)d_in[14];
    const float* bn_b = (const float*)d_in[15];
    const float* c1_W = (const float*)d_in[16];
    const float* c1_b = (const float*)d_in[17];
    const float* W_fc = (const float*)d_in[18];
    const float* b_fc = (const float*)d_in[19];
    float* out = (float*)d_out;

    const int CAP_SMEM  = 300*64*4;
    const int GEN_SMEM  = (128 + 16384)*4;
    const int CONV_SMEM = (8192 + 16384 + 16384)*4;
    const int C1_SMEM   = (16384 + 32768 + 512)*4;
    const int FC_SMEM   = (16384 + 8192 + 1024)*4;
    cudaFuncSetAttribute((const void*)k_cap_red,  cudaFuncAttributeMaxDynamicSharedMemorySize, CAP_SMEM);
    cudaFuncSetAttribute((const void*)k_gen,      cudaFuncAttributeMaxDynamicSharedMemorySize, GEN_SMEM);
    cudaFuncSetAttribute((const void*)k_conv<63>, cudaFuncAttributeMaxDynamicSharedMemorySize, CONV_SMEM);
    cudaFuncSetAttribute((const void*)k_conv<62>, cudaFuncAttributeMaxDynamicSharedMemorySize, CONV_SMEM);
    cudaFuncSetAttribute((const void*)k_c1<63>,   cudaFuncAttributeMaxDynamicSharedMemorySize, C1_SMEM);
    cudaFuncSetAttribute((const void*)k_c1<62>,   cudaFuncAttributeMaxDynamicSharedMemorySize, C1_SMEM);
    cudaFuncSetAttribute((const void*)k_fc_max,   cudaFuncAttributeMaxDynamicSharedMemorySize, FC_SMEM);

    k_img_prep<<<NI, 256>>>(img_embed, W_ri, b_ri);
    k_gen<<<NI*2, 256, GEN_SMEM>>>(mk_W, mk_b, wn_g, wn_b);
    k_cap_red<<<NB, 256, CAP_SMEM>>>(cap_embed, W_rt, b_rt, W_fc, c1_W, ca_W);

    // block j = 0 (T 64 -> 63)
    k_conv<63><<<dim3(NB/4, NI), 256, CONV_SMEM>>>(0);
    k_c1<63><<<dim3(NB/4, NI), 256, C1_SMEM>>>(bn_g, bn_b, c1_b, 0);

    // block j = 1 (T 63 -> 62)
    k_conv<62><<<dim3(NB/4, NI), 256, CONV_SMEM>>>(1);
    k_c1<62><<<dim3(NB/4, NI), 256, C1_SMEM>>>(bn_g, bn_b, c1_b, 1);

    // W_fc + max over time (16 captions per CTA), then normalize + dot
    k_fc_max<<<dim3(8, NB/16, NI), 256, FC_SMEM>>>(b_fc);
    k_final<<<dim3(NB, NI), 256>>>(out);
}

// round 6
// speedup vs baseline: 1.3097x; 1.1633x over previous
#include <cuda_runtime.h>
#include <cuda_bf16.h>
#include <math.h>

#define NI 32     // images
#define NB 128    // captions
#define RR 128    // reduced channels
#define LL 1024   // latent
#define TT 64     // initial time

typedef unsigned long long u64;
typedef unsigned int u32;

// ---------------- packed f32x2 helpers (sm_103a FFMA2 path) ----------------
__device__ __forceinline__ u64 pk2(float lo, float hi) {
    u64 v; asm("mov.b64 %0, {%1, %2};" : "=l"(v) : "f"(lo), "f"(hi)); return v;
}
__device__ __forceinline__ u64 bc2(float x) { return pk2(x, x); }
__device__ __forceinline__ void up2(u64 v, float& lo, float& hi) {
    asm("mov.b64 {%0, %1}, %2;" : "=f"(lo), "=f"(hi) : "l"(v));
}
__device__ __forceinline__ u64 fma2(u64 a, u64 b, u64 c) {
    u64 d; asm("fma.rn.f32x2 %0, %1, %2, %3;" : "=l"(d) : "l"(a), "l"(b), "l"(c)); return d;
}

// ---------------- warp mma.sync bf16 (legacy HMMA path; sm_80+ baseline PTX) -------
__device__ __forceinline__ void mma16816(float c[4], const u32 a[4], const u32 b[2]) {
    asm volatile("mma.sync.aligned.m16n8k16.row.col.f32.bf16.bf16.f32 "
                 "{%0,%1,%2,%3}, {%4,%5,%6,%7}, {%8,%9}, {%0,%1,%2,%3};"
                 : "+f"(c[0]), "+f"(c[1]), "+f"(c[2]), "+f"(c[3])
                 : "r"(a[0]), "r"(a[1]), "r"(a[2]), "r"(a[3]), "r"(b[0]), "r"(b[1]));
}

// ---------------- device scratch (static globals; no allocation) ----------------
__device__ float  g_cap_red[NB*RR*TT];                 // [b][o][64]
__device__ float  g_img_global[NI*LL];
__device__ float  g_inorm[NI];
__device__ float  g_img_vec[NI*RR];
__device__ float  g_kern[NI*2*128*128];                // [(i*2+j)][cik][o]
__device__ float  g_caWT[2*128*128];                   // [j][cik][o]
__device__ float  g_c1WT[2*256*128];                   // [j][ch][o]
__device__ double g_stats[2*NI*512];                   // per-j per-image per-channel sum/sumsq
__device__ float  g_h[(size_t)NI*NB*256*64];           // conv outputs (px|ax)
__device__ float  g_x[(size_t)NI*NB*128*64];           // block activations
__device__ u32    g_xh[(size_t)NI*NB*64*64];           // x split bf16 hi, [ib][t][c-pair]
__device__ u32    g_xl[(size_t)NI*NB*64*64];           // x split bf16 lo
__device__ float  g_y[(size_t)NI*NB*1024];             // max-pooled pre-norm

// ---------------- stage 1: image prep (mean, norm, hypernet base) ----------------
__global__ __launch_bounds__(256) void k_img_prep(const float* __restrict__ img_embed,
                                                  const float* __restrict__ W_ri,
                                                  const float* __restrict__ b_ri) {
    __shared__ float gsh[LL];
    __shared__ float red[256];
    int i = blockIdx.x, tid = threadIdx.x;
    float ssq = 0.f;
    for (int c = tid; c < LL; c += 256) {
        float s = 0.f;
        #pragma unroll
        for (int t = 0; t < 36; t++) s += img_embed[((size_t)i*36 + t)*LL + c];
        s *= (1.0f/36.0f);
        gsh[c] = s;
        g_img_global[i*LL + c] = s;
        ssq += s*s;
    }
    red[tid] = ssq; __syncthreads();
    for (int s = 128; s > 0; s >>= 1) { if (tid < s) red[tid] += red[tid+s]; __syncthreads(); }
    if (tid == 0) g_inorm[i] = sqrtf(red[0]);
    if (tid < RR) {
        int o = tid;
        float acc = b_ri[o];
        const float* w = W_ri + (size_t)o * LL;
        for (int c = 0; c < LL; c++) acc = fmaf(w[c], gsh[c], acc);
        g_img_vec[i*RR + o] = acc;
    }
}

// ---------------- stage 2: hypernet kernel generation + weight BN (+ stats zero) ----
__global__ __launch_bounds__(256) void k_gen(const float* __restrict__ mk_W,
                                             const float* __restrict__ mk_b,
                                             const float* __restrict__ wn_g,
                                             const float* __restrict__ wn_b) {
    extern __shared__ float sm[];
    float* base = sm;          // 128
    float* kraw = sm + 128;    // 16384
    int i = blockIdx.x >> 1, j = blockIdx.x & 1, tid = threadIdx.x;
    for (int z = blockIdx.x*256 + tid; z < 2*NI*512; z += 64*256) g_stats[z] = 0.0;
    if (tid < RR) base[tid] = g_img_vec[i*RR + tid];
    __syncthreads();
    for (int f = tid; f < 16384; f += 256) {
        float acc = mk_b[j*16384 + f];
        const float* w = mk_W + ((size_t)j*16384 + f)*128;
        #pragma unroll 4
        for (int c = 0; c < 128; c++) acc = fmaf(w[c], base[c], acc);
        kraw[f] = acc;
    }
    __syncthreads();
    if (tid < RR) {
        int o = tid;
        const float* kr = kraw + o*128;
        float s = 0.f, s2 = 0.f;
        for (int c = 0; c < 128; c++) { float v = kr[c]; s += v; s2 += v*v; }
        float m   = s * (1.f/128.f);
        float var = s2 * (1.f/128.f) - m*m;
        float a   = wn_g[j*RR+o] * rsqrtf(var + 1e-5f);
        float bb  = wn_b[j*RR+o] - a*m;
        float* dst = g_kern + ((size_t)(i*2+j))*16384;    // [cik][o]
        for (int cik = 0; cik < 128; cik++) dst[cik*128 + o] = fmaf(a, kr[cik], bb);
    }
}

// ---------------- stage 3: caption reduction + weight transposes ----------------
__global__ __launch_bounds__(256) void k_cap_red(const float* __restrict__ cap_embed,
                                                 const float* __restrict__ W_rt,
                                                 const float* __restrict__ b_rt,
                                                 const float* __restrict__ c1_W,
                                                 const float* __restrict__ ca_W) {
    extern __shared__ float sm[];
    float* ce = sm;                      // [c 300][t 64]
    int b = blockIdx.x, tid = threadIdx.x;
    {
        const int N2 = 2*256*128, N3 = 2*128*128;
        for (int t = b*256 + tid; t < N2+N3; t += NB*256) {
            if (t < N2) {
                int j = t >> 15; int v = t & 32767; int ch = v >> 7, o = v & 127;
                g_c1WT[t] = c1_W[(j*128 + o)*256 + ch];
            } else {
                int u = t - N2;
                int j = u >> 14; int v = u & 16383; int cik = v >> 7, o = v & 127;
                g_caWT[u] = ca_W[(j*128 + o)*128 + cik];
            }
        }
    }
    for (int idx = tid; idx < 300*TT; idx += 256) {
        int c = idx >> 6, t = idx & 63;
        ce[idx] = cap_embed[(size_t)b*TT*300 + t*300 + c];
    }
    __syncthreads();
    for (int q = tid; q < RR*16; q += 256) {
        int o = q >> 4, tq = (q & 15) * 4;
        float a0 = 0.f, a1 = 0.f, a2 = 0.f, a3 = 0.f;
        const float* w = W_rt + o*300;
        for (int c = 0; c < 300; c++) {
            float wv = w[c];
            float4 x4 = *(const float4*)(ce + c*TT + tq);
            a0 = fmaf(wv, x4.x, a0); a1 = fmaf(wv, x4.y, a1);
            a2 = fmaf(wv, x4.z, a2); a3 = fmaf(wv, x4.w, a3);
        }
        float bo = b_rt[o];
        float* dst = g_cap_red + ((size_t)b*RR + o)*TT + tq;
        dst[0] = a0 + bo; dst[1] = a1 + bo; dst[2] = a2 + bo; dst[3] = a3 + bo;
    }
}

// ---------------- stage 4: grouped convs + BN stats, 4 captions per CTA ----------
template<int TOUT>
__global__ __launch_bounds__(256) void k_conv(int j) {
    extern __shared__ float sm[];
    float* xs  = sm;                    // [128][64]
    float* wpx = sm + 8192;             // [cik][o]
    float* wax = sm + 8192 + 16384;     // [cik][o]
    int bq = blockIdx.x, i = blockIdx.y, tid = threadIdx.x;
    const float* kp = g_kern + (size_t)(i*2 + j)*16384;
    const float* ka = g_caWT + (size_t)j*16384;
    for (int idx = tid; idx < 16384; idx += 256) { wpx[idx] = kp[idx]; wax[idx] = ka[idx]; }

    int opair = tid & 63, th = tid >> 6;       // 64 o-pairs x 4 t-slots
    const float* xg = xs + (opair >> 5) * 4096;
    const int wo = opair * 2;
    float sp0=0.f, sp0q=0.f, sp1=0.f, sp1q=0.f;
    float sa0=0.f, sa0q=0.f, sa1=0.f, sa1q=0.f;

    for (int bs = 0; bs < 4; bs++) {
        int b = bq*4 + bs;
        const float* xin = (j == 0) ? (g_cap_red + (size_t)b*8192)
                                    : (g_x + ((size_t)i*NB + b)*8192);
        __syncthreads();   // xs reuse: previous iteration fully consumed
        for (int idx = tid; idx < 8192; idx += 256) xs[idx] = xin[idx];
        __syncthreads();

        for (int chunk = th; chunk < 8; chunk += 4) {
            int t0 = chunk * 8;
            u64 accP[8], accA[8];
            #pragma unroll
            for (int t = 0; t < 8; t++) { accP[t] = 0ull; accA[t] = 0ull; }
            #pragma unroll 2
            for (int ci = 0; ci < 64; ci++) {
                const float* xr = xg + ci*64 + t0;
                float4 xlo = *(const float4*)xr;
                float4 xhi = *(const float4*)(xr + 4);
                float x8v = xr[8];   // may read 1 past row for last chunk; discarded
                u64 xx[9];
                xx[0]=bc2(xlo.x); xx[1]=bc2(xlo.y); xx[2]=bc2(xlo.z); xx[3]=bc2(xlo.w);
                xx[4]=bc2(xhi.x); xx[5]=bc2(xhi.y); xx[6]=bc2(xhi.z); xx[7]=bc2(xhi.w);
                xx[8]=bc2(x8v);
                u64 wp0 = *(const u64*)(wpx + (ci*2  )*128 + wo);
                u64 wp1 = *(const u64*)(wpx + (ci*2+1)*128 + wo);
                u64 wa0 = *(const u64*)(wax + (ci*2  )*128 + wo);
                u64 wa1 = *(const u64*)(wax + (ci*2+1)*128 + wo);
                #pragma unroll
                for (int t = 0; t < 8; t++) {
                    accP[t] = fma2(wp0, xx[t],   accP[t]);
                    accP[t] = fma2(wp1, xx[t+1], accP[t]);
                    accA[t] = fma2(wa0, xx[t],   accA[t]);
                    accA[t] = fma2(wa1, xx[t+1], accA[t]);
                }
            }
            float* hp = g_h + ((size_t)(i*NB + b))*16384;   // [256 ch][64 t]
            #pragma unroll
            for (int t = 0; t < 8; t++) {
                int tg = t0 + t;
                if (tg < TOUT) {
                    float p0, p1, a0, a1;
                    up2(accP[t], p0, p1);
                    up2(accA[t], a0, a1);
                    hp[(wo  )*64 + tg] = p0;
                    hp[(wo+1)*64 + tg] = p1;
                    hp[(128+wo  )*64 + tg] = a0;
                    hp[(128+wo+1)*64 + tg] = a1;
                    sp0 += p0; sp0q += p0*p0; sp1 += p1; sp1q += p1*p1;
                    sa0 += a0; sa0q += a0*a0; sa1 += a1; sa1q += a1*a1;
                }
            }
        }
    }
    double* st = g_stats + ((size_t)j*NI + i)*512;
    atomicAdd(st + (wo      )*2    , (double)sp0);
    atomicAdd(st + (wo      )*2 + 1, (double)sp0q);
    atomicAdd(st + (wo+1    )*2    , (double)sp1);
    atomicAdd(st + (wo+1    )*2 + 1, (double)sp1q);
    atomicAdd(st + (128+wo  )*2    , (double)sa0);
    atomicAdd(st + (128+wo  )*2 + 1, (double)sa0q);
    atomicAdd(st + (128+wo+1)*2    , (double)sa1);
    atomicAdd(st + (128+wo+1)*2 + 1, (double)sa1q);
}

// ---------------- stage 5: BN+ReLU + 1x1 mixing conv (c1), 4 captions per CTA ------
template<int TOUT>
__global__ __launch_bounds__(256) void k_c1(const float* __restrict__ bn_g,
                                            const float* __restrict__ bn_b,
                                            const float* __restrict__ c1_b, int j) {
    extern __shared__ float sm[];
    float* hs = sm;                       // [256][64]
    float* ws = sm + 16384;               // [ch][o]
    float* aa = sm + 49152;               // 256
    float* bb = sm + 49408;               // 256
    int bq = blockIdx.x, i = blockIdx.y, tid = threadIdx.x;
    {
        double s  = g_stats[((size_t)j*NI + i)*512 + tid*2];
        double s2 = g_stats[((size_t)j*NI + i)*512 + tid*2 + 1];
        double n  = (double)(NB*TOUT);
        float m   = (float)(s / n);
        float var = (float)(s2 / n) - m*m;
        float a   = bn_g[j*256 + tid] * rsqrtf(var + 1e-5f);
        aa[tid] = a;
        bb[tid] = bn_b[j*256 + tid] - a*m;
    }
    const float* wsrc = g_c1WT + j*32768;
    for (int idx = tid; idx < 32768; idx += 256) ws[idx] = wsrc[idx];

    int lane = tid & 31, wp = tid >> 5;
    int t0 = wp * 8;
    int oA = 2*lane, oB = 64 + 2*lane;
    float cbA0 = c1_b[j*128+oA],   cbA1 = c1_b[j*128+oA+1];
    float cbB0 = c1_b[j*128+oB],   cbB1 = c1_b[j*128+oB+1];

    for (int bs = 0; bs < 4; bs++) {
        int b = bq*4 + bs;
        const float* hsrc = g_h + (size_t)(i*NB + b)*16384;
        __syncthreads();   // hs reuse
        for (int idx = tid; idx < 16384; idx += 256) {
            int ch = idx >> 6, t = idx & 63;
            float v = fmaf(aa[ch], hsrc[idx], bb[ch]);
            hs[idx] = (t < TOUT) ? fmaxf(v, 0.f) : 0.f;
        }
        __syncthreads();

        u64 acc0[8], acc1[8];
        #pragma unroll
        for (int t = 0; t < 8; t++) { acc0[t] = 0ull; acc1[t] = 0ull; }
        #pragma unroll 2
        for (int ch = 0; ch < 256; ch++) {
            u64 w0 = *(const u64*)(ws + ch*128 + 2*lane);
            u64 w1 = *(const u64*)(ws + ch*128 + 64 + 2*lane);
            float4 xa = *(const float4*)(hs + ch*64 + t0);
            float4 xb = *(const float4*)(hs + ch*64 + t0 + 4);
            u64 xx[8];
            xx[0]=bc2(xa.x); xx[1]=bc2(xa.y); xx[2]=bc2(xa.z); xx[3]=bc2(xa.w);
            xx[4]=bc2(xb.x); xx[5]=bc2(xb.y); xx[6]=bc2(xb.z); xx[7]=bc2(xb.w);
            #pragma unroll
            for (int t = 0; t < 8; t++) {
                acc0[t] = fma2(w0, xx[t], acc0[t]);
                acc1[t] = fma2(w1, xx[t], acc1[t]);
            }
        }
        float* xout = g_x + (size_t)(i*NB + b)*8192;
        #pragma unroll
        for (int t = 0; t < 8; t++) {
            int tg = t0 + t;
            if (tg < TOUT) {
                float lo, hi;
                up2(acc0[t], lo, hi);
                xout[oA*64 + tg] = lo + cbA0; xout[(oA+1)*64 + tg] = hi + cbA1;
                up2(acc1[t], lo, hi);
                xout[oB*64 + tg] = lo + cbB0; xout[(oB+1)*64 + tg] = hi + cbB1;
            }
        }
    }
}

// ---------------- stage 6a: split x -> bf16 hi/lo, transposed to [t][c] ------------
__global__ __launch_bounds__(256) void k_split() {
    __shared__ float sx[128*65];
    int ib = blockIdx.y*NB + blockIdx.x, tid = threadIdx.x;
    const float* xin = g_x + (size_t)ib*8192;
    for (int idx = tid; idx < 8192; idx += 256) {
        int c = idx >> 6, t = idx & 63;
        sx[c*65 + t] = xin[idx];
    }
    __syncthreads();
    u32* dh = g_xh + (size_t)ib*4096;
    u32* dl = g_xl + (size_t)ib*4096;
    for (int u = tid; u < 4096; u += 256) {
        int t = u >> 6, cp = u & 63;
        int c = cp*2;
        float v0 = (t < 62) ? sx[c*65 + t]     : 0.f;
        float v1 = (t < 62) ? sx[(c+1)*65 + t] : 0.f;
        __nv_bfloat16 h0 = __float2bfloat16(v0);
        __nv_bfloat16 h1 = __float2bfloat16(v1);
        __nv_bfloat16 l0 = __float2bfloat16(v0 - __bfloat162float(h0));
        __nv_bfloat16 l1 = __float2bfloat16(v1 - __bfloat162float(h1));
        dh[u] = (u32)__bfloat16_as_ushort(h0) | ((u32)__bfloat16_as_ushort(h1) << 16);
        dl[u] = (u32)__bfloat16_as_ushort(l0) | ((u32)__bfloat16_as_ushort(l1) << 16);
    }
}

// ---------------- stage 6b: W_fc GEMM via mma.sync bf16 (split) + max-over-t -------
// smem layout (bytes), row stride 272B (=136 bf16) for conflict-free fragment LDS:
#define FC_WH 0
#define FC_WL 34816
#define FC_XH 69632
#define FC_XL 87040
#define FC_RED 104448
#define FC_SMEM_TOTAL 105472

__global__ __launch_bounds__(256) void k_fc_mma(const float* __restrict__ W_fc,
                                                const float* __restrict__ b_fc) {
    extern __shared__ char smc[];
    int lt = blockIdx.x, bg = blockIdx.y, i = blockIdx.z;
    int tid = threadIdx.x, wid = tid >> 5, lane = tid & 31;
    int g = lane >> 2, t4 = lane & 3;
    int warpM = wid >> 1, warpN = wid & 1;   // 4 m-warps x 2 n-warps

    // split W_fc tile [128 m][128 c] -> bf16 hi/lo in padded smem [m][136]
    const float* Wsrc = W_fc + (size_t)lt*128*128;
    for (int idx = tid; idx < 16384; idx += 256) {
        int m = idx >> 7, c = idx & 127;
        float v = Wsrc[idx];
        __nv_bfloat16 h = __float2bfloat16(v);
        __nv_bfloat16 l = __float2bfloat16(v - __bfloat162float(h));
        *(unsigned short*)(smc + FC_WH + m*272 + c*2) = __bfloat16_as_ushort(h);
        *(unsigned short*)(smc + FC_WL + m*272 + c*2) = __bfloat16_as_ushort(l);
    }
    float bfc = (tid < 128) ? b_fc[lt*128 + tid] : 0.f;
    float* redbuf = (float*)(smc + FC_RED);   // [2][128]

    const char* Abase = smc + (warpM*32 + g)*272;
    const char* Bbase = smc + (warpN*32 + g)*272;

    for (int bs = 0; bs < 16; bs++) {
        int b = bg*16 + bs;
        size_t ib = (size_t)i*NB + b;
        __syncthreads();   // X/red reuse
        {
            const uint4* sh = (const uint4*)(g_xh + ib*4096);
            const uint4* sl = (const uint4*)(g_xl + ib*4096);
            #pragma unroll
            for (int r = 0; r < 4; r++) {
                int u = tid + r*256;         // 0..1023 : row t = u/16, seg = u%16
                int t = u >> 4, sgm = u & 15;
                *(uint4*)(smc + FC_XH + t*272 + sgm*16) = sh[u];
                *(uint4*)(smc + FC_XL + t*272 + sgm*16) = sl[u];
            }
        }
        __syncthreads();

        float C[2][4][4];
        #pragma unroll
        for (int ms = 0; ms < 2; ms++)
            #pragma unroll
            for (int ns = 0; ns < 4; ns++)
                #pragma unroll
                for (int q = 0; q < 4; q++) C[ms][ns][q] = 0.f;

        #pragma unroll
        for (int term = 0; term < 3; term++) {
            const char* As = Abase + ((term == 1) ? FC_WL : FC_WH);
            const char* Bs = Bbase + ((term == 2) ? (FC_XL - FC_WH) : (FC_XH - FC_WH));
            #pragma unroll
            for (int kc = 0; kc < 8; kc++) {
                int kb = (kc*16 + t4*2) * 2;      // byte offset of bf16 pair
                u32 A[2][4], B[4][2];
                #pragma unroll
                for (int ms = 0; ms < 2; ms++) {
                    const char* p = As + ms*16*272 + kb;
                    A[ms][0] = *(const u32*)(p);
                    A[ms][1] = *(const u32*)(p + 8*272);
                    A[ms][2] = *(const u32*)(p + 16);
                    A[ms][3] = *(const u32*)(p + 8*272 + 16);
                }
                #pragma unroll
                for (int ns = 0; ns < 4; ns++) {
                    const char* p = Bs + ns*8*272 + kb;
                    B[ns][0] = *(const u32*)(p);
                    B[ns][1] = *(const u32*)(p + 16);
                }
                #pragma unroll
                for (int ms = 0; ms < 2; ms++)
                    #pragma unroll
                    for (int ns = 0; ns < 4; ns++)
                        mma16816(C[ms][ns], A[ms], B[ns]);
            }
        }

        // fused max over t (mask t>=62), quad-shuffle + 2-warpN smem reduce
        #pragma unroll
        for (int ms = 0; ms < 2; ms++) {
            float mA = -1e30f, mB = -1e30f;
            #pragma unroll
            for (int ns = 0; ns < 4; ns++) {
                int tg = warpN*32 + ns*8 + t4*2;
                if (tg < 62)     { mA = fmaxf(mA, C[ms][ns][0]); mB = fmaxf(mB, C[ms][ns][2]); }
                if (tg + 1 < 62) { mA = fmaxf(mA, C[ms][ns][1]); mB = fmaxf(mB, C[ms][ns][3]); }
            }
            mA = fmaxf(mA, __shfl_xor_sync(0xffffffffu, mA, 1));
            mA = fmaxf(mA, __shfl_xor_sync(0xffffffffu, mA, 2));
            mB = fmaxf(mB, __shfl_xor_sync(0xffffffffu, mB, 1));
            mB = fmaxf(mB, __shfl_xor_sync(0xffffffffu, mB, 2));
            if (t4 == 0) {
                int row = warpM*32 + ms*16 + g;
                redbuf[warpN*128 + row]     = mA;
                redbuf[warpN*128 + row + 8] = mB;
            }
        }
        __syncthreads();
        if (tid < 128) {
            float y = fmaxf(redbuf[tid], redbuf[128 + tid]) + bfc;
            g_y[ib*1024 + lt*128 + tid] = y;
        }
    }
}

// ---------------- stage 7: normalize + dot ----------------
__global__ __launch_bounds__(256) void k_final(float* __restrict__ out) {
    __shared__ float r1[256], r2[256];
    int b = blockIdx.x, i = blockIdx.y, tid = threadIdx.x;
    const float* y = g_y + (size_t)(i*NB + b)*1024;
    const float* g = g_img_global + i*LL;
    float d = 0.f, ss = 0.f;
    for (int l = tid; l < 1024; l += 256) { float yv = y[l]; d = fmaf(yv, g[l], d); ss = fmaf(yv, yv, ss); }
    r1[tid] = d; r2[tid] = ss; __syncthreads();
    for (int s = 128; s > 0; s >>= 1) {
        if (tid < s) { r1[tid] += r1[tid+s]; r2[tid] += r2[tid+s]; }
        __syncthreads();
    }
    if (tid == 0) out[i*NB + b] = r1[0] / (sqrtf(r2[0]) * g_inorm[i]);
}

// ---------------- launch ----------------
extern "C" void kernel_launch(void* const* d_in, const int* in_sizes, int n_in,
                              void* d_out, int out_size) {
    (void)in_sizes; (void)n_in; (void)out_size;
    const float* img_embed = (const float*)d_in[0];
    const float* cap_embed = (const float*)d_in[1];
    const float* W_ri = (const float*)d_in[2];
    const float* b_ri = (const float*)d_in[3];
    const float* W_rt = (const float*)d_in[4];
    const float* b_rt = (const float*)d_in[5];
    const float* mk_W = (const float*)d_in[6];
    const float* mk_b = (const float*)d_in[7];
    // d_in[8]=mbias_W, d_in[9]=mbias_b, d_in[13]=ca_b: exactly cancelled by training-mode BN
    const float* wn_g = (const float*)d_in[10];
    const float* wn_b = (const float*)d_in[11];
    const float* ca_W = (const float*)d_in[12];
    const float* bn_g = (const float*)d_in[14];
    const float* bn_b = (const float*)d_in[15];
    const float* c1_W = (const float*)d_in[16];
    const float* c1_b = (const float*)d_in[17];
    const float* W_fc = (const float*)d_in[18];
    const float* b_fc = (const float*)d_in[19];
    float* out = (float*)d_out;

    const int CAP_SMEM  = 300*64*4;
    const int GEN_SMEM  = (128 + 16384)*4;
    const int CONV_SMEM = (8192 + 16384 + 16384)*4;
    const int C1_SMEM   = (16384 + 32768 + 512)*4;
    cudaFuncSetAttribute((const void*)k_cap_red,  cudaFuncAttributeMaxDynamicSharedMemorySize, CAP_SMEM);
    cudaFuncSetAttribute((const void*)k_gen,      cudaFuncAttributeMaxDynamicSharedMemorySize, GEN_SMEM);
    cudaFuncSetAttribute((const void*)k_conv<63>, cudaFuncAttributeMaxDynamicSharedMemorySize, CONV_SMEM);
    cudaFuncSetAttribute((const void*)k_conv<62>, cudaFuncAttributeMaxDynamicSharedMemorySize, CONV_SMEM);
    cudaFuncSetAttribute((const void*)k_c1<63>,   cudaFuncAttributeMaxDynamicSharedMemorySize, C1_SMEM);
    cudaFuncSetAttribute((const void*)k_c1<62>,   cudaFuncAttributeMaxDynamicSharedMemorySize, C1_SMEM);
    cudaFuncSetAttribute((const void*)k_fc_mma,   cudaFuncAttributeMaxDynamicSharedMemorySize, FC_SMEM_TOTAL);

    k_img_prep<<<NI, 256>>>(img_embed, W_ri, b_ri);
    k_gen<<<NI*2, 256, GEN_SMEM>>>(mk_W, mk_b, wn_g, wn_b);
    k_cap_red<<<NB, 256, CAP_SMEM>>>(cap_embed, W_rt, b_rt, c1_W, ca_W);

    // block j = 0 (T 64 -> 63)
    k_conv<63><<<dim3(NB/4, NI), 256, CONV_SMEM>>>(0);
    k_c1<63><<<dim3(NB/4, NI), 256, C1_SMEM>>>(bn_g, bn_b, c1_b, 0);

    // block j = 1 (T 63 -> 62)
    k_conv<62><<<dim3(NB/4, NI), 256, CONV_SMEM>>>(1);
    k_c1<62><<<dim3(NB/4, NI), 256, C1_SMEM>>>(bn_g, bn_b, c1_b, 1);

    // split to bf16 hi/lo [t][c], tensor-core W_fc + max (16 captions/CTA), finalize
    k_split<<<dim3(NB, NI), 256>>>();
    k_fc_mma<<<dim3(8, NB/16, NI), 256, FC_SMEM_TOTAL>>>(W_fc, b_fc);
    k_final<<<dim3(NB, NI), 256>>>(out);
}

// round 7
// speedup vs baseline: 1.6928x; 1.2925x over previous
#include <cuda_runtime.h>
#include <cuda_bf16.h>
#include <math.h>

#define NI 32     // images
#define NB 128    // captions
#define RR 128    // reduced channels
#define LL 1024   // latent
#define TT 64     // initial time

typedef unsigned long long u64;
typedef unsigned int u32;

// ---------------- packed f32x2 helpers (sm_103a FFMA2 path) ----------------
__device__ __forceinline__ u64 pk2(float lo, float hi) {
    u64 v; asm("mov.b64 %0, {%1, %2};" : "=l"(v) : "f"(lo), "f"(hi)); return v;
}
__device__ __forceinline__ u64 bc2(float x) { return pk2(x, x); }
__device__ __forceinline__ void up2(u64 v, float& lo, float& hi) {
    asm("mov.b64 {%0, %1}, %2;" : "=f"(lo), "=f"(hi) : "l"(v));
}
__device__ __forceinline__ u64 fma2(u64 a, u64 b, u64 c) {
    u64 d; asm("fma.rn.f32x2 %0, %1, %2, %3;" : "=l"(d) : "l"(a), "l"(b), "l"(c)); return d;
}

// ---------------- warp mma.sync bf16 (legacy HMMA path; sm_80+ baseline PTX) -------
__device__ __forceinline__ void mma16816(float c[4], const u32 a[4], const u32 b[2]) {
    asm volatile("mma.sync.aligned.m16n8k16.row.col.f32.bf16.bf16.f32 "
                 "{%0,%1,%2,%3}, {%4,%5,%6,%7}, {%8,%9}, {%0,%1,%2,%3};"
                 : "+f"(c[0]), "+f"(c[1]), "+f"(c[2]), "+f"(c[3])
                 : "r"(a[0]), "r"(a[1]), "r"(a[2]), "r"(a[3]), "r"(b[0]), "r"(b[1]));
}

// ---------------- device scratch (static globals; no allocation) ----------------
__device__ float  g_cap_red[NB*RR*TT];                 // [b][o][64]
__device__ float  g_img_global[NI*LL];
__device__ float  g_inorm[NI];
__device__ float  g_img_vec[NI*RR];
__device__ float  g_kern[NI*2*128*128];                // [(i*2+j)][cik][o]
__device__ float  g_caWT[2*128*128];                   // [j][cik][o]
__device__ double g_stats[2*NI*512];                   // per-j per-image per-channel sum/sumsq
__device__ float  g_h[(size_t)NI*NB*64*256];           // conv outputs, [ib][t][256ch]
__device__ float  g_x[(size_t)NI*NB*128*64];           // block activations [c][t]
__device__ u32    g_xh[(size_t)NI*NB*64*64];           // x split bf16 hi, [ib][t][c-pair]
__device__ u32    g_xl[(size_t)NI*NB*64*64];           // x split bf16 lo
__device__ float  g_y[(size_t)NI*NB*1024];             // max-pooled pre-norm

// ---------------- stage 1: image prep (mean, norm, hypernet base) ----------------
__global__ __launch_bounds__(256) void k_img_prep(const float* __restrict__ img_embed,
                                                  const float* __restrict__ W_ri,
                                                  const float* __restrict__ b_ri) {
    __shared__ float gsh[LL];
    __shared__ float red[256];
    int i = blockIdx.x, tid = threadIdx.x;
    float ssq = 0.f;
    for (int c = tid; c < LL; c += 256) {
        float s = 0.f;
        #pragma unroll
        for (int t = 0; t < 36; t++) s += img_embed[((size_t)i*36 + t)*LL + c];
        s *= (1.0f/36.0f);
        gsh[c] = s;
        g_img_global[i*LL + c] = s;
        ssq += s*s;
    }
    red[tid] = ssq; __syncthreads();
    for (int s = 128; s > 0; s >>= 1) { if (tid < s) red[tid] += red[tid+s]; __syncthreads(); }
    if (tid == 0) g_inorm[i] = sqrtf(red[0]);
    if (tid < RR) {
        int o = tid;
        float acc = b_ri[o];
        const float* w = W_ri + (size_t)o * LL;
        for (int c = 0; c < LL; c++) acc = fmaf(w[c], gsh[c], acc);
        g_img_vec[i*RR + o] = acc;
    }
}

// ---------------- stage 2: hypernet kernel generation + weight BN (+ stats zero) ----
__global__ __launch_bounds__(256) void k_gen(const float* __restrict__ mk_W,
                                             const float* __restrict__ mk_b,
                                             const float* __restrict__ wn_g,
                                             const float* __restrict__ wn_b) {
    extern __shared__ float sm[];
    float* base = sm;          // 128
    float* kraw = sm + 128;    // 16384
    int i = blockIdx.x >> 1, j = blockIdx.x & 1, tid = threadIdx.x;
    for (int z = blockIdx.x*256 + tid; z < 2*NI*512; z += 64*256) g_stats[z] = 0.0;
    if (tid < RR) base[tid] = g_img_vec[i*RR + tid];
    __syncthreads();
    for (int f = tid; f < 16384; f += 256) {
        float acc = mk_b[j*16384 + f];
        const float* w = mk_W + ((size_t)j*16384 + f)*128;
        #pragma unroll 4
        for (int c = 0; c < 128; c++) acc = fmaf(w[c], base[c], acc);
        kraw[f] = acc;
    }
    __syncthreads();
    if (tid < RR) {
        int o = tid;
        const float* kr = kraw + o*128;
        float s = 0.f, s2 = 0.f;
        for (int c = 0; c < 128; c++) { float v = kr[c]; s += v; s2 += v*v; }
        float m   = s * (1.f/128.f);
        float var = s2 * (1.f/128.f) - m*m;
        float a   = wn_g[j*RR+o] * rsqrtf(var + 1e-5f);
        float bb  = wn_b[j*RR+o] - a*m;
        float* dst = g_kern + ((size_t)(i*2+j))*16384;    // [cik][o]
        for (int cik = 0; cik < 128; cik++) dst[cik*128 + o] = fmaf(a, kr[cik], bb);
    }
}

// ---------------- stage 3: caption reduction + weight transposes ----------------
__global__ __launch_bounds__(256) void k_cap_red(const float* __restrict__ cap_embed,
                                                 const float* __restrict__ W_rt,
                                                 const float* __restrict__ b_rt,
                                                 const float* __restrict__ ca_W) {
    extern __shared__ float sm[];
    float* ce = sm;                      // [c 300][t 64]
    int b = blockIdx.x, tid = threadIdx.x;
    {
        const int N3 = 2*128*128;
        for (int u = b*256 + tid; u < N3; u += NB*256) {
            int j = u >> 14; int v = u & 16383; int cik = v >> 7, o = v & 127;
            g_caWT[u] = ca_W[(j*128 + o)*128 + cik];
        }
    }
    for (int idx = tid; idx < 300*TT; idx += 256) {
        int c = idx >> 6, t = idx & 63;
        ce[idx] = cap_embed[(size_t)b*TT*300 + t*300 + c];
    }
    __syncthreads();
    for (int q = tid; q < RR*16; q += 256) {
        int o = q >> 4, tq = (q & 15) * 4;
        float a0 = 0.f, a1 = 0.f, a2 = 0.f, a3 = 0.f;
        const float* w = W_rt + o*300;
        for (int c = 0; c < 300; c++) {
            float wv = w[c];
            float4 x4 = *(const float4*)(ce + c*TT + tq);
            a0 = fmaf(wv, x4.x, a0); a1 = fmaf(wv, x4.y, a1);
            a2 = fmaf(wv, x4.z, a2); a3 = fmaf(wv, x4.w, a3);
        }
        float bo = b_rt[o];
        float* dst = g_cap_red + ((size_t)b*RR + o)*TT + tq;
        dst[0] = a0 + bo; dst[1] = a1 + bo; dst[2] = a2 + bo; dst[3] = a3 + bo;
    }
}

// ---------------- stage 4: grouped convs + BN stats, 4 captions per CTA ----------
// stores h TRANSPOSED: [ib][t][256 ch] for the mma c1 consumer
template<int TOUT>
__global__ __launch_bounds__(256) void k_conv(int j) {
    extern __shared__ float sm[];
    float* xs  = sm;                    // [128][64]
    float* wpx = sm + 8192;             // [cik][o]
    float* wax = sm + 8192 + 16384;     // [cik][o]
    int bq = blockIdx.x, i = blockIdx.y, tid = threadIdx.x;
    const float* kp = g_kern + (size_t)(i*2 + j)*16384;
    const float* ka = g_caWT + (size_t)j*16384;
    for (int idx = tid; idx < 16384; idx += 256) { wpx[idx] = kp[idx]; wax[idx] = ka[idx]; }

    int opair = tid & 63, th = tid >> 6;       // 64 o-pairs x 4 t-slots
    const float* xg = xs + (opair >> 5) * 4096;
    const int wo = opair * 2;
    float sp0=0.f, sp0q=0.f, sp1=0.f, sp1q=0.f;
    float sa0=0.f, sa0q=0.f, sa1=0.f, sa1q=0.f;

    for (int bs = 0; bs < 4; bs++) {
        int b = bq*4 + bs;
        const float* xin = (j == 0) ? (g_cap_red + (size_t)b*8192)
                                    : (g_x + ((size_t)i*NB + b)*8192);
        __syncthreads();   // xs reuse: previous iteration fully consumed
        for (int idx = tid; idx < 8192; idx += 256) xs[idx] = xin[idx];
        __syncthreads();

        for (int chunk = th; chunk < 8; chunk += 4) {
            int t0 = chunk * 8;
            u64 accP[8], accA[8];
            #pragma unroll
            for (int t = 0; t < 8; t++) { accP[t] = 0ull; accA[t] = 0ull; }
            #pragma unroll 2
            for (int ci = 0; ci < 64; ci++) {
                const float* xr = xg + ci*64 + t0;
                float4 xlo = *(const float4*)xr;
                float4 xhi = *(const float4*)(xr + 4);
                float x8v = xr[8];   // may read 1 past row for last chunk; discarded
                u64 xx[9];
                xx[0]=bc2(xlo.x); xx[1]=bc2(xlo.y); xx[2]=bc2(xlo.z); xx[3]=bc2(xlo.w);
                xx[4]=bc2(xhi.x); xx[5]=bc2(xhi.y); xx[6]=bc2(xhi.z); xx[7]=bc2(xhi.w);
                xx[8]=bc2(x8v);
                u64 wp0 = *(const u64*)(wpx + (ci*2  )*128 + wo);
                u64 wp1 = *(const u64*)(wpx + (ci*2+1)*128 + wo);
                u64 wa0 = *(const u64*)(wax + (ci*2  )*128 + wo);
                u64 wa1 = *(const u64*)(wax + (ci*2+1)*128 + wo);
                #pragma unroll
                for (int t = 0; t < 8; t++) {
                    accP[t] = fma2(wp0, xx[t],   accP[t]);
                    accP[t] = fma2(wp1, xx[t+1], accP[t]);
                    accA[t] = fma2(wa0, xx[t],   accA[t]);
                    accA[t] = fma2(wa1, xx[t+1], accA[t]);
                }
            }
            float* hp = g_h + ((size_t)(i*NB + b))*16384;   // [64 t][256 ch]
            #pragma unroll
            for (int t = 0; t < 8; t++) {
                int tg = t0 + t;
                if (tg < TOUT) {
                    float p0, p1, a0, a1;
                    up2(accP[t], p0, p1);
                    up2(accA[t], a0, a1);
                    hp[tg*256 + wo      ] = p0;
                    hp[tg*256 + wo + 1  ] = p1;
                    hp[tg*256 + 128 + wo    ] = a0;
                    hp[tg*256 + 128 + wo + 1] = a1;
                    sp0 += p0; sp0q += p0*p0; sp1 += p1; sp1q += p1*p1;
                    sa0 += a0; sa0q += a0*a0; sa1 += a1; sa1q += a1*a1;
                }
            }
        }
    }
    double* st = g_stats + ((size_t)j*NI + i)*512;
    atomicAdd(st + (wo      )*2    , (double)sp0);
    atomicAdd(st + (wo      )*2 + 1, (double)sp0q);
    atomicAdd(st + (wo+1    )*2    , (double)sp1);
    atomicAdd(st + (wo+1    )*2 + 1, (double)sp1q);
    atomicAdd(st + (128+wo  )*2    , (double)sa0);
    atomicAdd(st + (128+wo  )*2 + 1, (double)sa0q);
    atomicAdd(st + (128+wo+1)*2    , (double)sa1);
    atomicAdd(st + (128+wo+1)*2 + 1, (double)sa1q);
}

// ---------------- stage 5: BN+ReLU + c1 via mma.sync (split-bf16) ----------------
// A = c1_W[j] [128 o][256 ch], B = BN-ReLU(h) [64 t][256 ch]; row stride 528B
#define C1_WH 0
#define C1_WL 67584
#define C1_BH 135168
#define C1_BL 168960
#define C1_AB 202752
#define C1_SMEM_TOTAL 204800

template<int TOUT>
__global__ __launch_bounds__(256) void k_c1_mma(const float* __restrict__ bn_g,
                                                const float* __restrict__ bn_b,
                                                const float* __restrict__ c1_b,
                                                const float* __restrict__ c1_W, int j) {
    extern __shared__ char smc[];
    float* aa = (float*)(smc + C1_AB);
    float* bb = aa + 256;
    int bg = blockIdx.x, i = blockIdx.y, tid = threadIdx.x;
    int wid = tid >> 5, lane = tid & 31, g = lane >> 2, t4 = lane & 3;
    int warpM = wid >> 1, warpN = wid & 1;

    // BN coefficients from conv stats
    {
        double s  = g_stats[((size_t)j*NI + i)*512 + tid*2];
        double s2 = g_stats[((size_t)j*NI + i)*512 + tid*2 + 1];
        double n  = (double)(NB*TOUT);
        float m   = (float)(s / n);
        float var = (float)(s2 / n) - m*m;
        float a   = bn_g[j*256 + tid] * rsqrtf(var + 1e-5f);
        aa[tid] = a;
        bb[tid] = bn_b[j*256 + tid] - a*m;
    }
    // A tiles: c1_W[j] [128][256] -> bf16 hi/lo, padded rows
    const float* Wsrc = c1_W + (size_t)j*128*256;
    for (int idx = tid; idx < 32768; idx += 256) {
        int o = idx >> 8, ch = idx & 255;
        float v = Wsrc[idx];
        __nv_bfloat16 h = __float2bfloat16(v);
        __nv_bfloat16 l = __float2bfloat16(v - __bfloat162float(h));
        *(unsigned short*)(smc + C1_WH + o*528 + ch*2) = __bfloat16_as_ushort(h);
        *(unsigned short*)(smc + C1_WL + o*528 + ch*2) = __bfloat16_as_ushort(l);
    }
    // c1 bias for the 4 rows this thread writes
    float cb[2][2];
    #pragma unroll
    for (int ms = 0; ms < 2; ms++)
        #pragma unroll
        for (int hq = 0; hq < 2; hq++)
            cb[ms][hq] = c1_b[j*128 + warpM*32 + ms*16 + g + hq*8];

    for (int bs = 0; bs < 16; bs++) {
        int b = bg*16 + bs;
        const float* hsrc = g_h + (size_t)(i*NB + b)*16384;   // [t][256]
        __syncthreads();   // B reuse (also orders A/aa on first iter)
        for (int idx = tid; idx < 16384; idx += 256) {
            int t = idx >> 8, ch = idx & 255;
            float v = fmaf(aa[ch], hsrc[idx], bb[ch]);
            v = (t < TOUT) ? fmaxf(v, 0.f) : 0.f;
            __nv_bfloat16 hh = __float2bfloat16(v);
            __nv_bfloat16 ll = __float2bfloat16(v - __bfloat162float(hh));
            *(unsigned short*)(smc + C1_BH + t*528 + ch*2) = __bfloat16_as_ushort(hh);
            *(unsigned short*)(smc + C1_BL + t*528 + ch*2) = __bfloat16_as_ushort(ll);
        }
        __syncthreads();

        float C[2][4][4];
        #pragma unroll
        for (int ms = 0; ms < 2; ms++)
            #pragma unroll
            for (int ns = 0; ns < 4; ns++)
                #pragma unroll
                for (int q = 0; q < 4; q++) C[ms][ns][q] = 0.f;

        #pragma unroll
        for (int term = 0; term < 3; term++) {
            const char* As = smc + ((term == 1) ? C1_WL : C1_WH) + (warpM*32 + g)*528;
            const char* Bs = smc + ((term == 2) ? C1_BL : C1_BH) + (warpN*32 + g)*528;
            #pragma unroll
            for (int kc = 0; kc < 16; kc++) {
                int kb = (kc*16 + t4*2) * 2;
                u32 A[2][4], B[4][2];
                #pragma unroll
                for (int ms = 0; ms < 2; ms++) {
                    const char* p = As + ms*16*528 + kb;
                    A[ms][0] = *(const u32*)(p);
                    A[ms][1] = *(const u32*)(p + 8*528);
                    A[ms][2] = *(const u32*)(p + 16);
                    A[ms][3] = *(const u32*)(p + 8*528 + 16);
                }
                #pragma unroll
                for (int ns = 0; ns < 4; ns++) {
                    const char* p = Bs + ns*8*528 + kb;
                    B[ns][0] = *(const u32*)(p);
                    B[ns][1] = *(const u32*)(p + 16);
                }
                #pragma unroll
                for (int ms = 0; ms < 2; ms++)
                    #pragma unroll
                    for (int ns = 0; ns < 4; ns++)
                        mma16816(C[ms][ns], A[ms], B[ns]);
            }
        }

        float* xout = g_x + (size_t)(i*NB + b)*8192;   // [o 128][t 64]
        #pragma unroll
        for (int ms = 0; ms < 2; ms++) {
            int row0 = warpM*32 + ms*16 + g;
            #pragma unroll
            for (int ns = 0; ns < 4; ns++) {
                int tg = warpN*32 + ns*8 + t4*2;
                if (tg < TOUT) {
                    xout[row0*64 + tg]       = C[ms][ns][0] + cb[ms][0];
                    xout[(row0+8)*64 + tg]   = C[ms][ns][2] + cb[ms][1];
                }
                if (tg + 1 < TOUT) {
                    xout[row0*64 + tg + 1]     = C[ms][ns][1] + cb[ms][0];
                    xout[(row0+8)*64 + tg + 1] = C[ms][ns][3] + cb[ms][1];
                }
            }
        }
    }
}

// ---------------- stage 6a: split x -> bf16 hi/lo, transposed to [t][c] ------------
__global__ __launch_bounds__(256) void k_split() {
    __shared__ float sx[128*65];
    int ib = blockIdx.y*NB + blockIdx.x, tid = threadIdx.x;
    const float* xin = g_x + (size_t)ib*8192;
    for (int idx = tid; idx < 8192; idx += 256) {
        int c = idx >> 6, t = idx & 63;
        sx[c*65 + t] = xin[idx];
    }
    __syncthreads();
    u32* dh = g_xh + (size_t)ib*4096;
    u32* dl = g_xl + (size_t)ib*4096;
    for (int u = tid; u < 4096; u += 256) {
        int t = u >> 6, cp = u & 63;
        int c = cp*2;
        float v0 = (t < 62) ? sx[c*65 + t]     : 0.f;
        float v1 = (t < 62) ? sx[(c+1)*65 + t] : 0.f;
        __nv_bfloat16 h0 = __float2bfloat16(v0);
        __nv_bfloat16 h1 = __float2bfloat16(v1);
        __nv_bfloat16 l0 = __float2bfloat16(v0 - __bfloat162float(h0));
        __nv_bfloat16 l1 = __float2bfloat16(v1 - __bfloat162float(h1));
        dh[u] = (u32)__bfloat16_as_ushort(h0) | ((u32)__bfloat16_as_ushort(h1) << 16);
        dl[u] = (u32)__bfloat16_as_ushort(l0) | ((u32)__bfloat16_as_ushort(l1) << 16);
    }
}

// ---------------- stage 6b: W_fc GEMM via mma.sync bf16 (split) + max-over-t -------
#define FC_WH 0
#define FC_WL 34816
#define FC_XH 69632
#define FC_XL 87040
#define FC_RED 104448
#define FC_SMEM_TOTAL 105472

__global__ __launch_bounds__(256) void k_fc_mma(const float* __restrict__ W_fc,
                                                const float* __restrict__ b_fc) {
    extern __shared__ char smc[];
    int lt = blockIdx.x, bg = blockIdx.y, i = blockIdx.z;
    int tid = threadIdx.x, wid = tid >> 5, lane = tid & 31;
    int g = lane >> 2, t4 = lane & 3;
    int warpM = wid >> 1, warpN = wid & 1;   // 4 m-warps x 2 n-warps

    const float* Wsrc = W_fc + (size_t)lt*128*128;
    for (int idx = tid; idx < 16384; idx += 256) {
        int m = idx >> 7, c = idx & 127;
        float v = Wsrc[idx];
        __nv_bfloat16 h = __float2bfloat16(v);
        __nv_bfloat16 l = __float2bfloat16(v - __bfloat162float(h));
        *(unsigned short*)(smc + FC_WH + m*272 + c*2) = __bfloat16_as_ushort(h);
        *(unsigned short*)(smc + FC_WL + m*272 + c*2) = __bfloat16_as_ushort(l);
    }
    float bfc = (tid < 128) ? b_fc[lt*128 + tid] : 0.f;
    float* redbuf = (float*)(smc + FC_RED);   // [2][128]

    const char* Abase = smc + (warpM*32 + g)*272;
    const char* Bbase = smc + (warpN*32 + g)*272;

    for (int bs = 0; bs < 16; bs++) {
        int b = bg*16 + bs;
        size_t ib = (size_t)i*NB + b;
        __syncthreads();   // X/red reuse
        {
            const uint4* sh = (const uint4*)(g_xh + ib*4096);
            const uint4* sl = (const uint4*)(g_xl + ib*4096);
            #pragma unroll
            for (int r = 0; r < 4; r++) {
                int u = tid + r*256;         // 0..1023 : row t = u/16, seg = u%16
                int t = u >> 4, sgm = u & 15;
                *(uint4*)(smc + FC_XH + t*272 + sgm*16) = sh[u];
                *(uint4*)(smc + FC_XL + t*272 + sgm*16) = sl[u];
            }
        }
        __syncthreads();

        float C[2][4][4];
        #pragma unroll
        for (int ms = 0; ms < 2; ms++)
            #pragma unroll
            for (int ns = 0; ns < 4; ns++)
                #pragma unroll
                for (int q = 0; q < 4; q++) C[ms][ns][q] = 0.f;

        #pragma unroll
        for (int term = 0; term < 3; term++) {
            const char* As = Abase + ((term == 1) ? FC_WL : FC_WH);
            const char* Bs = Bbase + ((term == 2) ? (FC_XL - FC_WH) : (FC_XH - FC_WH));
            #pragma unroll
            for (int kc = 0; kc < 8; kc++) {
                int kb = (kc*16 + t4*2) * 2;      // byte offset of bf16 pair
                u32 A[2][4], B[4][2];
                #pragma unroll
                for (int ms = 0; ms < 2; ms++) {
                    const char* p = As + ms*16*272 + kb;
                    A[ms][0] = *(const u32*)(p);
                    A[ms][1] = *(const u32*)(p + 8*272);
                    A[ms][2] = *(const u32*)(p + 16);
                    A[ms][3] = *(const u32*)(p + 8*272 + 16);
                }
                #pragma unroll
                for (int ns = 0; ns < 4; ns++) {
                    const char* p = Bs + ns*8*272 + kb;
                    B[ns][0] = *(const u32*)(p);
                    B[ns][1] = *(const u32*)(p + 16);
                }
                #pragma unroll
                for (int ms = 0; ms < 2; ms++)
                    #pragma unroll
                    for (int ns = 0; ns < 4; ns++)
                        mma16816(C[ms][ns], A[ms], B[ns]);
            }
        }

        // fused max over t (mask t>=62), quad-shuffle + 2-warpN smem reduce
        #pragma unroll
        for (int ms = 0; ms < 2; ms++) {
            float mA = -1e30f, mB = -1e30f;
            #pragma unroll
            for (int ns = 0; ns < 4; ns++) {
                int tg = warpN*32 + ns*8 + t4*2;
                if (tg < 62)     { mA = fmaxf(mA, C[ms][ns][0]); mB = fmaxf(mB, C[ms][ns][2]); }
                if (tg + 1 < 62) { mA = fmaxf(mA, C[ms][ns][1]); mB = fmaxf(mB, C[ms][ns][3]); }
            }
            mA = fmaxf(mA, __shfl_xor_sync(0xffffffffu, mA, 1));
            mA = fmaxf(mA, __shfl_xor_sync(0xffffffffu, mA, 2));
            mB = fmaxf(mB, __shfl_xor_sync(0xffffffffu, mB, 1));
            mB = fmaxf(mB, __shfl_xor_sync(0xffffffffu, mB, 2));
            if (t4 == 0) {
                int row = warpM*32 + ms*16 + g;
                redbuf[warpN*128 + row]     = mA;
                redbuf[warpN*128 + row + 8] = mB;
            }
        }
        __syncthreads();
        if (tid < 128) {
            float y = fmaxf(redbuf[tid], redbuf[128 + tid]) + bfc;
            g_y[ib*1024 + lt*128 + tid] = y;
        }
    }
}

// ---------------- stage 7: normalize + dot ----------------
__global__ __launch_bounds__(256) void k_final(float* __restrict__ out) {
    __shared__ float r1[256], r2[256];
    int b = blockIdx.x, i = blockIdx.y, tid = threadIdx.x;
    const float* y = g_y + (size_t)(i*NB + b)*1024;
    const float* g = g_img_global + i*LL;
    float d = 0.f, ss = 0.f;
    for (int l = tid; l < 1024; l += 256) { float yv = y[l]; d = fmaf(yv, g[l], d); ss = fmaf(yv, yv, ss); }
    r1[tid] = d; r2[tid] = ss; __syncthreads();
    for (int s = 128; s > 0; s >>= 1) {
        if (tid < s) { r1[tid] += r1[tid+s]; r2[tid] += r2[tid+s]; }
        __syncthreads();
    }
    if (tid == 0) out[i*NB + b] = r1[0] / (sqrtf(r2[0]) * g_inorm[i]);
}

// ---------------- launch ----------------
extern "C" void kernel_launch(void* const* d_in, const int* in_sizes, int n_in,
                              void* d_out, int out_size) {
    (void)in_sizes; (void)n_in; (void)out_size;
    const float* img_embed = (const float*)d_in[0];
    const float* cap_embed = (const float*)d_in[1];
    const float* W_ri = (const float*)d_in[2];
    const float* b_ri = (const float*)d_in[3];
    const float* W_rt = (const float*)d_in[4];
    const float* b_rt = (const float*)d_in[5];
    const float* mk_W = (const float*)d_in[6];
    const float* mk_b = (const float*)d_in[7];
    // d_in[8]=mbias_W, d_in[9]=mbias_b, d_in[13]=ca_b: exactly cancelled by training-mode BN
    const float* wn_g = (const float*)d_in[10];
    const float* wn_b = (const float*)d_in[11];
    const float* ca_W = (const float*)d_in[12];
    const float* bn_g = (const float*)d_in[14];
    const float* bn_b = (const float*)d_in[15];
    const float* c1_W = (const float*)d_in[16];
    const float* c1_b = (const float*)d_in[17];
    const float* W_fc = (const float*)d_in[18];
    const float* b_fc = (const float*)d_in[19];
    float* out = (float*)d_out;

    const int CAP_SMEM  = 300*64*4;
    const int GEN_SMEM  = (128 + 16384)*4;
    const int CONV_SMEM = (8192 + 16384 + 16384)*4;
    cudaFuncSetAttribute((const void*)k_cap_red,    cudaFuncAttributeMaxDynamicSharedMemorySize, CAP_SMEM);
    cudaFuncSetAttribute((const void*)k_gen,        cudaFuncAttributeMaxDynamicSharedMemorySize, GEN_SMEM);
    cudaFuncSetAttribute((const void*)k_conv<63>,   cudaFuncAttributeMaxDynamicSharedMemorySize, CONV_SMEM);
    cudaFuncSetAttribute((const void*)k_conv<62>,   cudaFuncAttributeMaxDynamicSharedMemorySize, CONV_SMEM);
    cudaFuncSetAttribute((const void*)k_c1_mma<63>, cudaFuncAttributeMaxDynamicSharedMemorySize, C1_SMEM_TOTAL);
    cudaFuncSetAttribute((const void*)k_c1_mma<62>, cudaFuncAttributeMaxDynamicSharedMemorySize, C1_SMEM_TOTAL);
    cudaFuncSetAttribute((const void*)k_fc_mma,     cudaFuncAttributeMaxDynamicSharedMemorySize, FC_SMEM_TOTAL);

    k_img_prep<<<NI, 256>>>(img_embed, W_ri, b_ri);
    k_gen<<<NI*2, 256, GEN_SMEM>>>(mk_W, mk_b, wn_g, wn_b);
    k_cap_red<<<NB, 256, CAP_SMEM>>>(cap_embed, W_rt, b_rt, ca_W);

    // block j = 0 (T 64 -> 63)
    k_conv<63><<<dim3(NB/4, NI), 256, CONV_SMEM>>>(0);
    k_c1_mma<63><<<dim3(NB/16, NI), 256, C1_SMEM_TOTAL>>>(bn_g, bn_b, c1_b, c1_W, 0);

    // block j = 1 (T 63 -> 62)
    k_conv<62><<<dim3(NB/4, NI), 256, CONV_SMEM>>>(1);
    k_c1_mma<62><<<dim3(NB/16, NI), 256, C1_SMEM_TOTAL>>>(bn_g, bn_b, c1_b, c1_W, 1);

    // split to bf16 hi/lo [t][c], tensor-core W_fc + max (16 captions/CTA), finalize
    k_split<<<dim3(NB, NI), 256>>>();
    k_fc_mma<<<dim3(8, NB/16, NI), 256, FC_SMEM_TOTAL>>>(W_fc, b_fc);
    k_final<<<dim3(NB, NI), 256>>>(out);
}

// round 8
// speedup vs baseline: 2.0072x; 1.1857x over previous
#include <cuda_runtime.h>
#include <cuda_bf16.h>
#include <math.h>

#define NI 32     // images
#define NB 128    // captions
#define RR 128    // reduced channels
#define LL 1024   // latent
#define TT 64     // initial time

typedef unsigned long long u64;
typedef unsigned int u32;
typedef unsigned short u16;

// ---------------- warp mma.sync bf16 (legacy HMMA path; sm_80+ baseline PTX) -------
__device__ __forceinline__ void mma16816(float c[4], const u32 a[4], const u32 b[2]) {
    asm volatile("mma.sync.aligned.m16n8k16.row.col.f32.bf16.bf16.f32 "
                 "{%0,%1,%2,%3}, {%4,%5,%6,%7}, {%8,%9}, {%0,%1,%2,%3};"
                 : "+f"(c[0]), "+f"(c[1]), "+f"(c[2]), "+f"(c[3])
                 : "r"(a[0]), "r"(a[1]), "r"(a[2]), "r"(a[3]), "r"(b[0]), "r"(b[1]));
}
__device__ __forceinline__ void bsplit(float v, u16& h, u16& l) {
    __nv_bfloat16 hb = __float2bfloat16(v);
    __nv_bfloat16 lb = __float2bfloat16(v - __bfloat162float(hb));
    h = __bfloat16_as_ushort(hb); l = __bfloat16_as_ushort(lb);
}

// ---------------- device scratch (static globals; no allocation) ----------------
__device__ float  g_img_global[NI*LL];
__device__ float  g_inorm[NI];
__device__ float  g_img_vec[NI*RR];
__device__ float  g_kernT[NI*2*4*64*64];               // [(i2j)][g*2+k][o'][ci]
__device__ float  g_caT[2*4*64*64];                    // [j][g*2+k][row][ci]
__device__ double g_stats[2*NI*512];                   // per-j per-image per-channel sum/sumsq
__device__ float  g_h[(size_t)NI*NB*64*256];           // conv outputs, [ib][t][256ch]
__device__ __align__(16) u16 g_crh[NB*64*128];         // cap_red split hi, [b][t][c]
__device__ __align__(16) u16 g_crl[NB*64*128];
__device__ __align__(16) u16 g_xh[(size_t)NI*NB*64*128];  // x split hi, [ib][t][c]
__device__ __align__(16) u16 g_xl[(size_t)NI*NB*64*128];
__device__ float  g_y[(size_t)NI*NB*1024];             // max-pooled pre-norm

// ---------------- stage 1: image prep (mean, norm, hypernet base) ----------------
__global__ __launch_bounds__(256) void k_img_prep(const float* __restrict__ img_embed,
                                                  const float* __restrict__ W_ri,
                                                  const float* __restrict__ b_ri) {
    __shared__ float gsh[LL];
    __shared__ float red[256];
    int i = blockIdx.x, tid = threadIdx.x;
    float ssq = 0.f;
    for (int c = tid; c < LL; c += 256) {
        float s = 0.f;
        #pragma unroll
        for (int t = 0; t < 36; t++) s += img_embed[((size_t)i*36 + t)*LL + c];
        s *= (1.0f/36.0f);
        gsh[c] = s;
        g_img_global[i*LL + c] = s;
        ssq += s*s;
    }
    red[tid] = ssq; __syncthreads();
    for (int s = 128; s > 0; s >>= 1) { if (tid < s) red[tid] += red[tid+s]; __syncthreads(); }
    if (tid == 0) g_inorm[i] = sqrtf(red[0]);
    if (tid < RR) {
        int o = tid;
        float acc = b_ri[o];
        const float* w = W_ri + (size_t)o * LL;
        for (int c = 0; c < LL; c++) acc = fmaf(w[c], gsh[c], acc);
        g_img_vec[i*RR + o] = acc;
    }
}

// ---------------- stage 2: hypernet kernel generation + weight BN (+ stats zero) ----
// emits g_kernT in [g*2+k][o'][ci] layout for the conv mma A-build
__global__ __launch_bounds__(256) void k_gen(const float* __restrict__ mk_W,
                                             const float* __restrict__ mk_b,
                                             const float* __restrict__ wn_g,
                                             const float* __restrict__ wn_b) {
    extern __shared__ float sm[];
    float* base = sm;          // 128
    float* kraw = sm + 128;    // 16384
    int i = blockIdx.x >> 1, j = blockIdx.x & 1, tid = threadIdx.x;
    for (int z = blockIdx.x*256 + tid; z < 2*NI*512; z += 64*256) g_stats[z] = 0.0;
    if (tid < RR) base[tid] = g_img_vec[i*RR + tid];
    __syncthreads();
    for (int f = tid; f < 16384; f += 256) {
        float acc = mk_b[j*16384 + f];
        const float* w = mk_W + ((size_t)j*16384 + f)*128;
        #pragma unroll 4
        for (int c = 0; c < 128; c++) acc = fmaf(w[c], base[c], acc);
        kraw[f] = acc;
    }
    __syncthreads();
    if (tid < RR) {
        int o = tid, g = o >> 6, op = o & 63;
        const float* kr = kraw + o*128;
        float s = 0.f, s2 = 0.f;
        for (int c = 0; c < 128; c++) { float v = kr[c]; s += v; s2 += v*v; }
        float m   = s * (1.f/128.f);
        float var = s2 * (1.f/128.f) - m*m;
        float a   = wn_g[j*RR+o] * rsqrtf(var + 1e-5f);
        float bb  = wn_b[j*RR+o] - a*m;
        float* dst = g_kernT + (size_t)(i*2+j)*16384;
        for (int cik = 0; cik < 128; cik++) {
            int ci = cik >> 1, k = cik & 1;
            dst[((g*2+k)*64 + op)*64 + ci] = fmaf(a, kr[cik], bb);
        }
    }
}

// ---------------- stage 3: caption reduction (split-bf16 out) + ca_W transform -----
__global__ __launch_bounds__(256) void k_cap_red(const float* __restrict__ cap_embed,
                                                 const float* __restrict__ W_rt,
                                                 const float* __restrict__ b_rt,
                                                 const float* __restrict__ ca_W) {
    extern __shared__ float sm[];
    float* ce = sm;                      // [c 300][t 64]
    int b = blockIdx.x, tid = threadIdx.x;
    // ca_W -> [j][g*2+k][row][ci] (grid-stride over all blocks)
    for (int u = b*256 + tid; u < 32768; u += NB*256) {
        int ci = u & 63, row = (u >> 6) & 63, gk = (u >> 12) & 3, j2 = u >> 14;
        int o = (gk >> 1)*64 + row, k = gk & 1;
        g_caT[j2*16384 + (gk*64 + row)*64 + ci] = ca_W[((j2*128 + o)*64 + ci)*2 + k];
    }
    for (int idx = tid; idx < 300*TT; idx += 256) {
        int c = idx >> 6, t = idx & 63;
        ce[idx] = cap_embed[(size_t)b*TT*300 + t*300 + c];
    }
    __syncthreads();
    for (int q = tid; q < RR*16; q += 256) {
        int o = q >> 4, tq = (q & 15) * 4;
        float a0 = 0.f, a1 = 0.f, a2 = 0.f, a3 = 0.f;
        const float* w = W_rt + o*300;
        for (int c = 0; c < 300; c++) {
            float wv = w[c];
            float4 x4 = *(const float4*)(ce + c*TT + tq);
            a0 = fmaf(wv, x4.x, a0); a1 = fmaf(wv, x4.y, a1);
            a2 = fmaf(wv, x4.z, a2); a3 = fmaf(wv, x4.w, a3);
        }
        float bo = b_rt[o];
        float vv[4] = {a0 + bo, a1 + bo, a2 + bo, a3 + bo};
        #pragma unroll
        for (int n = 0; n < 4; n++) {
            u16 h, l; bsplit(vv[n], h, l);
            g_crh[b*8192 + (tq + n)*128 + o] = h;
            g_crl[b*8192 + (tq + n)*128 + o] = l;
        }
    }
}

// ---------------- stage 4: grouped convs via mma.sync + BN stats, 16 capt/CTA ------
// A: [g*2+k][128 rows: 64 px-o | 64 ax-o][64 ci], 144B stride, hi/lo
// B: [65 t rows][128 c], 272B stride, hi/lo; kstep=1 offsets base by one row
#define CV_AH 0
#define CV_AL 73728
#define CV_BH 147456
#define CV_BL 165136
#define CV_SMEM_TOTAL 182816

template<int TOUT>
__global__ __launch_bounds__(256) void k_conv_mma(int j) {
    extern __shared__ char smc[];
    int bg = blockIdx.x, i = blockIdx.y, tid = threadIdx.x;
    int wid = tid >> 5, lane = tid & 31, gq = lane >> 2, t4 = lane & 3;
    int warpM = wid >> 1, warpN = wid & 1;

    // A build (coalesced reads from transformed layouts)
    const float* kt = g_kernT + (size_t)(i*2 + j)*16384;
    const float* ct = g_caT + (size_t)j*16384;
    for (int idx = tid; idx < 32768; idx += 256) {
        int ci = idx & 63, row = (idx >> 6) & 127, gk = idx >> 13;
        float v = (row < 64) ? kt[(gk*64 + row)*64 + ci]
                             : ct[(gk*64 + (row - 64))*64 + ci];
        u16 h, l; bsplit(v, h, l);
        int off = (gk*128 + row)*144 + ci*2;
        *(u16*)(smc + CV_AH + off) = h;
        *(u16*)(smc + CV_AL + off) = l;
    }

    float st_s[2][2][2], st_q[2][2][2];   // [g][ms][hq]
    #pragma unroll
    for (int g = 0; g < 2; g++)
        #pragma unroll
        for (int ms = 0; ms < 2; ms++)
            #pragma unroll
            for (int hq = 0; hq < 2; hq++) { st_s[g][ms][hq] = 0.f; st_q[g][ms][hq] = 0.f; }

    for (int bs = 0; bs < 16; bs++) {
        int b = bg*16 + bs;
        size_t ib = (size_t)i*NB + b;
        const u16* srcH = (j == 0) ? (g_crh + (size_t)b*8192) : (g_xh + ib*8192);
        const u16* srcL = (j == 0) ? (g_crl + (size_t)b*8192) : (g_xl + ib*8192);
        __syncthreads();   // protect previous B (and A on first iter)
        {
            const uint4* sh = (const uint4*)srcH;
            const uint4* sl = (const uint4*)srcL;
            #pragma unroll
            for (int r = 0; r < 4; r++) {
                int u = tid + r*256;
                int t = u >> 4, sgm = u & 15;
                *(uint4*)(smc + CV_BH + t*272 + sgm*16) = sh[u];
                *(uint4*)(smc + CV_BL + t*272 + sgm*16) = sl[u];
            }
            if (tid < 17) {
                *(uint4*)(smc + CV_BH + 64*272 + tid*16) = make_uint4(0,0,0,0);
                *(uint4*)(smc + CV_BL + 64*272 + tid*16) = make_uint4(0,0,0,0);
            }
        }
        __syncthreads();

        float* hp = g_h + ib*16384;   // [t][256]
        #pragma unroll
        for (int g = 0; g < 2; g++) {
            float C[2][4][4];
            #pragma unroll
            for (int ms = 0; ms < 2; ms++)
                #pragma unroll
                for (int ns = 0; ns < 4; ns++)
                    #pragma unroll
                    for (int q = 0; q < 4; q++) C[ms][ns][q] = 0.f;

            #pragma unroll
            for (int term = 0; term < 3; term++) {
                const char* Ab = smc + ((term == 1) ? CV_AL : CV_AH);
                const char* Bb = smc + ((term == 2) ? CV_BL : CV_BH);
                #pragma unroll
                for (int ks = 0; ks < 2; ks++) {
                    const char* As = Ab + ((g*2 + ks)*128 + warpM*32 + gq)*144;
                    const char* Bs = Bb + (warpN*32 + gq + ks)*272 + g*128;
                    #pragma unroll
                    for (int kc = 0; kc < 4; kc++) {
                        int kb = (kc*16 + t4*2)*2;
                        u32 A[2][4], B[4][2];
                        #pragma unroll
                        for (int ms = 0; ms < 2; ms++) {
                            const char* p = As + ms*16*144 + kb;
                            A[ms][0] = *(const u32*)(p);
                            A[ms][1] = *(const u32*)(p + 8*144);
                            A[ms][2] = *(const u32*)(p + 16);
                            A[ms][3] = *(const u32*)(p + 8*144 + 16);
                        }
                        #pragma unroll
                        for (int ns = 0; ns < 4; ns++) {
                            const char* p = Bs + ns*8*272 + kb;
                            B[ns][0] = *(const u32*)(p);
                            B[ns][1] = *(const u32*)(p + 16);
                        }
                        #pragma unroll
                        for (int ms = 0; ms < 2; ms++)
                            #pragma unroll
                            for (int ns = 0; ns < 4; ns++)
                                mma16816(C[ms][ns], A[ms], B[ns]);
                    }
                }
            }
            // epilogue: store h [t][256] + accumulate BN stats
            #pragma unroll
            for (int ms = 0; ms < 2; ms++) {
                int r0 = warpM*32 + ms*16 + gq;
                int r1 = r0 + 8;
                int chA = (r0 < 64) ? (g*64 + r0) : (128 + g*64 + r0 - 64);
                int chB = (r1 < 64) ? (g*64 + r1) : (128 + g*64 + r1 - 64);
                #pragma unroll
                for (int ns = 0; ns < 4; ns++) {
                    int tg = warpN*32 + ns*8 + t4*2;
                    if (tg < TOUT) {
                        float v0 = C[ms][ns][0], v2 = C[ms][ns][2];
                        hp[tg*256 + chA] = v0;
                        hp[tg*256 + chB] = v2;
                        st_s[g][ms][0] += v0; st_q[g][ms][0] += v0*v0;
                        st_s[g][ms][1] += v2; st_q[g][ms][1] += v2*v2;
                    }
                    if (tg + 1 < TOUT) {
                        float v1 = C[ms][ns][1], v3 = C[ms][ns][3];
                        hp[(tg+1)*256 + chA] = v1;
                        hp[(tg+1)*256 + chB] = v3;
                        st_s[g][ms][0] += v1; st_q[g][ms][0] += v1*v1;
                        st_s[g][ms][1] += v3; st_q[g][ms][1] += v3*v3;
                    }
                }
            }
        }
    }
    // reduce stats over t4 lanes, atomic once per (row, warpN)
    double* st = g_stats + ((size_t)j*NI + i)*512;
    #pragma unroll
    for (int g = 0; g < 2; g++)
        #pragma unroll
        for (int ms = 0; ms < 2; ms++)
            #pragma unroll
            for (int hq = 0; hq < 2; hq++) {
                float s = st_s[g][ms][hq], q = st_q[g][ms][hq];
                s += __shfl_xor_sync(0xffffffffu, s, 1);
                s += __shfl_xor_sync(0xffffffffu, s, 2);
                q += __shfl_xor_sync(0xffffffffu, q, 1);
                q += __shfl_xor_sync(0xffffffffu, q, 2);
                if (t4 == 0) {
                    int r = warpM*32 + ms*16 + gq + hq*8;
                    int ch = (r < 64) ? (g*64 + r) : (128 + g*64 + r - 64);
                    atomicAdd(st + ch*2,     (double)s);
                    atomicAdd(st + ch*2 + 1, (double)q);
                }
            }
}

// ---------------- stage 5: BN+ReLU + c1 via mma.sync; emits split-bf16 x ----------
#define C1_WH 0
#define C1_WL 67584
#define C1_BH 135168
#define C1_BL 168960
#define C1_AB 202752
#define C1_SMEM_TOTAL 204800

template<int TOUT>
__global__ __launch_bounds__(256) void k_c1_mma(const float* __restrict__ bn_g,
                                                const float* __restrict__ bn_b,
                                                const float* __restrict__ c1_b,
                                                const float* __restrict__ c1_W, int j) {
    extern __shared__ char smc[];
    float* aa = (float*)(smc + C1_AB);
    float* bb = aa + 256;
    int bg = blockIdx.x, i = blockIdx.y, tid = threadIdx.x;
    int wid = tid >> 5, lane = tid & 31, g = lane >> 2, t4 = lane & 3;
    int warpM = wid >> 1, warpN = wid & 1;

    {
        double s  = g_stats[((size_t)j*NI + i)*512 + tid*2];
        double s2 = g_stats[((size_t)j*NI + i)*512 + tid*2 + 1];
        double n  = (double)(NB*TOUT);
        float m   = (float)(s / n);
        float var = (float)(s2 / n) - m*m;
        float a   = bn_g[j*256 + tid] * rsqrtf(var + 1e-5f);
        aa[tid] = a;
        bb[tid] = bn_b[j*256 + tid] - a*m;
    }
    const float* Wsrc = c1_W + (size_t)j*128*256;
    for (int idx = tid; idx < 32768; idx += 256) {
        int o = idx >> 8, ch = idx & 255;
        u16 h, l; bsplit(Wsrc[idx], h, l);
        *(u16*)(smc + C1_WH + o*528 + ch*2) = h;
        *(u16*)(smc + C1_WL + o*528 + ch*2) = l;
    }
    float cb[2][2];
    #pragma unroll
    for (int ms = 0; ms < 2; ms++)
        #pragma unroll
        for (int hq = 0; hq < 2; hq++)
            cb[ms][hq] = c1_b[j*128 + warpM*32 + ms*16 + g + hq*8];

    for (int bs = 0; bs < 16; bs++) {
        int b = bg*16 + bs;
        size_t ib = (size_t)i*NB + b;
        const float* hsrc = g_h + ib*16384;   // [t][256]
        __syncthreads();
        for (int idx = tid; idx < 16384; idx += 256) {
            int t = idx >> 8, ch = idx & 255;
            float v = fmaf(aa[ch], hsrc[idx], bb[ch]);
            v = (t < TOUT) ? fmaxf(v, 0.f) : 0.f;
            u16 hh, ll; bsplit(v, hh, ll);
            *(u16*)(smc + C1_BH + t*528 + ch*2) = hh;
            *(u16*)(smc + C1_BL + t*528 + ch*2) = ll;
        }
        __syncthreads();

        float C[2][4][4];
        #pragma unroll
        for (int ms = 0; ms < 2; ms++)
            #pragma unroll
            for (int ns = 0; ns < 4; ns++)
                #pragma unroll
                for (int q = 0; q < 4; q++) C[ms][ns][q] = 0.f;

        #pragma unroll
        for (int term = 0; term < 3; term++) {
            const char* As = smc + ((term == 1) ? C1_WL : C1_WH) + (warpM*32 + g)*528;
            const char* Bs = smc + ((term == 2) ? C1_BL : C1_BH) + (warpN*32 + g)*528;
            #pragma unroll
            for (int kc = 0; kc < 16; kc++) {
                int kb = (kc*16 + t4*2) * 2;
                u32 A[2][4], B[4][2];
                #pragma unroll
                for (int ms = 0; ms < 2; ms++) {
                    const char* p = As + ms*16*528 + kb;
                    A[ms][0] = *(const u32*)(p);
                    A[ms][1] = *(const u32*)(p + 8*528);
                    A[ms][2] = *(const u32*)(p + 16);
                    A[ms][3] = *(const u32*)(p + 8*528 + 16);
                }
                #pragma unroll
                for (int ns = 0; ns < 4; ns++) {
                    const char* p = Bs + ns*8*528 + kb;
                    B[ns][0] = *(const u32*)(p);
                    B[ns][1] = *(const u32*)(p + 16);
                }
                #pragma unroll
                for (int ms = 0; ms < 2; ms++)
                    #pragma unroll
                    for (int ns = 0; ns < 4; ns++)
                        mma16816(C[ms][ns], A[ms], B[ns]);
            }
        }

        // epilogue: x -> split bf16 [t][c] (zeros for t >= TOUT)
        u16* xh = g_xh + ib*8192;
        u16* xl = g_xl + ib*8192;
        #pragma unroll
        for (int ms = 0; ms < 2; ms++) {
            int row0 = warpM*32 + ms*16 + g;
            #pragma unroll
            for (int ns = 0; ns < 4; ns++) {
                int tg = warpN*32 + ns*8 + t4*2;
                #pragma unroll
                for (int dt = 0; dt < 2; dt++) {
                    int t = tg + dt;
                    float vA = (t < TOUT) ? (C[ms][ns][dt]     + cb[ms][0]) : 0.f;
                    float vB = (t < TOUT) ? (C[ms][ns][dt + 2] + cb[ms][1]) : 0.f;
                    u16 h, l;
                    bsplit(vA, h, l);
                    xh[t*128 + row0]     = h; xl[t*128 + row0]     = l;
                    bsplit(vB, h, l);
                    xh[t*128 + row0 + 8] = h; xl[t*128 + row0 + 8] = l;
                }
            }
        }
    }
}

// ---------------- stage 6: W_fc GEMM via mma.sync bf16 (split) + max-over-t -------
#define FC_WH 0
#define FC_WL 34816
#define FC_XH 69632
#define FC_XL 87040
#define FC_RED 104448
#define FC_SMEM_TOTAL 105472

__global__ __launch_bounds__(256) void k_fc_mma(const float* __restrict__ W_fc,
                                                const float* __restrict__ b_fc) {
    extern __shared__ char smc[];
    int lt = blockIdx.x, bg = blockIdx.y, i = blockIdx.z;
    int tid = threadIdx.x, wid = tid >> 5, lane = tid & 31;
    int g = lane >> 2, t4 = lane & 3;
    int warpM = wid >> 1, warpN = wid & 1;

    const float* Wsrc = W_fc + (size_t)lt*128*128;
    for (int idx = tid; idx < 16384; idx += 256) {
        int m = idx >> 7, c = idx & 127;
        u16 h, l; bsplit(Wsrc[idx], h, l);
        *(u16*)(smc + FC_WH + m*272 + c*2) = h;
        *(u16*)(smc + FC_WL + m*272 + c*2) = l;
    }
    float bfc = (tid < 128) ? b_fc[lt*128 + tid] : 0.f;
    float* redbuf = (float*)(smc + FC_RED);   // [2][128]

    const char* Abase = smc + (warpM*32 + g)*272;
    const char* Bbase = smc + (warpN*32 + g)*272;

    for (int bs = 0; bs < 16; bs++) {
        int b = bg*16 + bs;
        size_t ib = (size_t)i*NB + b;
        __syncthreads();
        {
            const uint4* sh = (const uint4*)(g_xh + ib*8192);
            const uint4* sl = (const uint4*)(g_xl + ib*8192);
            #pragma unroll
            for (int r = 0; r < 4; r++) {
                int u = tid + r*256;
                int t = u >> 4, sgm = u & 15;
                *(uint4*)(smc + FC_XH + t*272 + sgm*16) = sh[u];
                *(uint4*)(smc + FC_XL + t*272 + sgm*16) = sl[u];
            }
        }
        __syncthreads();

        float C[2][4][4];
        #pragma unroll
        for (int ms = 0; ms < 2; ms++)
            #pragma unroll
            for (int ns = 0; ns < 4; ns++)
                #pragma unroll
                for (int q = 0; q < 4; q++) C[ms][ns][q] = 0.f;

        #pragma unroll
        for (int term = 0; term < 3; term++) {
            const char* As = Abase + ((term == 1) ? FC_WL : FC_WH);
            const char* Bs = Bbase + ((term == 2) ? (FC_XL - FC_WH) : (FC_XH - FC_WH));
            #pragma unroll
            for (int kc = 0; kc < 8; kc++) {
                int kb = (kc*16 + t4*2) * 2;
                u32 A[2][4], B[4][2];
                #pragma unroll
                for (int ms = 0; ms < 2; ms++) {
                    const char* p = As + ms*16*272 + kb;
                    A[ms][0] = *(const u32*)(p);
                    A[ms][1] = *(const u32*)(p + 8*272);
                    A[ms][2] = *(const u32*)(p + 16);
                    A[ms][3] = *(const u32*)(p + 8*272 + 16);
                }
                #pragma unroll
                for (int ns = 0; ns < 4; ns++) {
                    const char* p = Bs + ns*8*272 + kb;
                    B[ns][0] = *(const u32*)(p);
                    B[ns][1] = *(const u32*)(p + 16);
                }
                #pragma unroll
                for (int ms = 0; ms < 2; ms++)
                    #pragma unroll
                    for (int ns = 0; ns < 4; ns++)
                        mma16816(C[ms][ns], A[ms], B[ns]);
            }
        }

        #pragma unroll
        for (int ms = 0; ms < 2; ms++) {
            float mA = -1e30f, mB = -1e30f;
            #pragma unroll
            for (int ns = 0; ns < 4; ns++) {
                int tg = warpN*32 + ns*8 + t4*2;
                if (tg < 62)     { mA = fmaxf(mA, C[ms][ns][0]); mB = fmaxf(mB, C[ms][ns][2]); }
                if (tg + 1 < 62) { mA = fmaxf(mA, C[ms][ns][1]); mB = fmaxf(mB, C[ms][ns][3]); }
            }
            mA = fmaxf(mA, __shfl_xor_sync(0xffffffffu, mA, 1));
            mA = fmaxf(mA, __shfl_xor_sync(0xffffffffu, mA, 2));
            mB = fmaxf(mB, __shfl_xor_sync(0xffffffffu, mB, 1));
            mB = fmaxf(mB, __shfl_xor_sync(0xffffffffu, mB, 2));
            if (t4 == 0) {
                int row = warpM*32 + ms*16 + g;
                redbuf[warpN*128 + row]     = mA;
                redbuf[warpN*128 + row + 8] = mB;
            }
        }
        __syncthreads();
        if (tid < 128) {
            float y = fmaxf(redbuf[tid], redbuf[128 + tid]) + bfc;
            g_y[ib*1024 + lt*128 + tid] = y;
        }
    }
}

// ---------------- stage 7: normalize + dot ----------------
__global__ __launch_bounds__(256) void k_final(float* __restrict__ out) {
    __shared__ float r1[256], r2[256];
    int b = blockIdx.x, i = blockIdx.y, tid = threadIdx.x;
    const float* y = g_y + (size_t)(i*NB + b)*1024;
    const float* g = g_img_global + i*LL;
    float d = 0.f, ss = 0.f;
    for (int l = tid; l < 1024; l += 256) { float yv = y[l]; d = fmaf(yv, g[l], d); ss = fmaf(yv, yv, ss); }
    r1[tid] = d; r2[tid] = ss; __syncthreads();
    for (int s = 128; s > 0; s >>= 1) {
        if (tid < s) { r1[tid] += r1[tid+s]; r2[tid] += r2[tid+s]; }
        __syncthreads();
    }
    if (tid == 0) out[i*NB + b] = r1[0] / (sqrtf(r2[0]) * g_inorm[i]);
}

// ---------------- launch ----------------
extern "C" void kernel_launch(void* const* d_in, const int* in_sizes, int n_in,
                              void* d_out, int out_size) {
    (void)in_sizes; (void)n_in; (void)out_size;
    const float* img_embed = (const float*)d_in[0];
    const float* cap_embed = (const float*)d_in[1];
    const float* W_ri = (const float*)d_in[2];
    const float* b_ri = (const float*)d_in[3];
    const float* W_rt = (const float*)d_in[4];
    const float* b_rt = (const float*)d_in[5];
    const float* mk_W = (const float*)d_in[6];
    const float* mk_b = (const float*)d_in[7];
    // d_in[8]=mbias_W, d_in[9]=mbias_b, d_in[13]=ca_b: exactly cancelled by training-mode BN
    const float* wn_g = (const float*)d_in[10];
    const float* wn_b = (const float*)d_in[11];
    const float* ca_W = (const float*)d_in[12];
    const float* bn_g = (const float*)d_in[14];
    const float* bn_b = (const float*)d_in[15];
    const float* c1_W = (const float*)d_in[16];
    const float* c1_b = (const float*)d_in[17];
    const float* W_fc = (const float*)d_in[18];
    const float* b_fc = (const float*)d_in[19];
    float* out = (float*)d_out;

    const int CAP_SMEM  = 300*64*4;
    const int GEN_SMEM  = (128 + 16384)*4;
    cudaFuncSetAttribute((const void*)k_cap_red,      cudaFuncAttributeMaxDynamicSharedMemorySize, CAP_SMEM);
    cudaFuncSetAttribute((const void*)k_gen,          cudaFuncAttributeMaxDynamicSharedMemorySize, GEN_SMEM);
    cudaFuncSetAttribute((const void*)k_conv_mma<63>, cudaFuncAttributeMaxDynamicSharedMemorySize, CV_SMEM_TOTAL);
    cudaFuncSetAttribute((const void*)k_conv_mma<62>, cudaFuncAttributeMaxDynamicSharedMemorySize, CV_SMEM_TOTAL);
    cudaFuncSetAttribute((const void*)k_c1_mma<63>,   cudaFuncAttributeMaxDynamicSharedMemorySize, C1_SMEM_TOTAL);
    cudaFuncSetAttribute((const void*)k_c1_mma<62>,   cudaFuncAttributeMaxDynamicSharedMemorySize, C1_SMEM_TOTAL);
    cudaFuncSetAttribute((const void*)k_fc_mma,       cudaFuncAttributeMaxDynamicSharedMemorySize, FC_SMEM_TOTAL);

    k_img_prep<<<NI, 256>>>(img_embed, W_ri, b_ri);
    k_gen<<<NI*2, 256, GEN_SMEM>>>(mk_W, mk_b, wn_g, wn_b);
    k_cap_red<<<NB, 256, CAP_SMEM>>>(cap_embed, W_rt, b_rt, ca_W);

    // block j = 0 (T 64 -> 63)
    k_conv_mma<63><<<dim3(NB/16, NI), 256, CV_SMEM_TOTAL>>>(0);
    k_c1_mma<63><<<dim3(NB/16, NI), 256, C1_SMEM_TOTAL>>>(bn_g, bn_b, c1_b, c1_W, 0);

    // block j = 1 (T 63 -> 62)
    k_conv_mma<62><<<dim3(NB/16, NI), 256, CV_SMEM_TOTAL>>>(1);
    k_c1_mma<62><<<dim3(NB/16, NI), 256, C1_SMEM_TOTAL>>>(bn_g, bn_b, c1_b, c1_W, 1);

    // tensor-core W_fc + max (16 captions/CTA), then normalize + dot
    k_fc_mma<<<dim3(8, NB/16, NI), 256, FC_SMEM_TOTAL>>>(W_fc, b_fc);
    k_final<<<dim3(NB, NI), 256>>>(out);
}

// round 9
// speedup vs baseline: 2.4131x; 1.2023x over previous
#include <cuda_runtime.h>
#include <cuda_bf16.h>
#include <math.h>

#define NI 32     // images
#define NB 128    // captions
#define RR 128    // reduced channels
#define LL 1024   // latent
#define TT 64     // initial time

typedef unsigned long long u64;
typedef unsigned int u32;
typedef unsigned short u16;

// ---------------- warp mma.sync bf16 (legacy HMMA path; sm_80+ baseline PTX) -------
__device__ __forceinline__ void mma16816(float c[4], const u32 a[4], const u32 b[2]) {
    asm volatile("mma.sync.aligned.m16n8k16.row.col.f32.bf16.bf16.f32 "
                 "{%0,%1,%2,%3}, {%4,%5,%6,%7}, {%8,%9}, {%0,%1,%2,%3};"
                 : "+f"(c[0]), "+f"(c[1]), "+f"(c[2]), "+f"(c[3])
                 : "r"(a[0]), "r"(a[1]), "r"(a[2]), "r"(a[3]), "r"(b[0]), "r"(b[1]));
}
__device__ __forceinline__ void bsplit(float v, u16& h, u16& l) {
    __nv_bfloat16 hb = __float2bfloat16(v);
    __nv_bfloat16 lb = __float2bfloat16(v - __bfloat162float(hb));
    h = __bfloat16_as_ushort(hb); l = __bfloat16_as_ushort(lb);
}
__device__ __forceinline__ u32 pk16(u16 a, u16 b) { return (u32)a | ((u32)b << 16); }

// ---------------- device scratch (static globals; no allocation) ----------------
__device__ float  g_img_global[NI*LL];
__device__ float  g_inorm[NI];
__device__ float  g_img_vec[NI*RR];
__device__ float  g_kernT[NI*2*4*64*64];               // [(i2j)][g*2+k][o'][ci]
__device__ float  g_caT[2*4*64*64];                    // [j][g*2+k][row][ci]
__device__ double g_stats[2*NI*512];                   // per-j per-image per-channel sum/sumsq
__device__ float  g_h[(size_t)NI*NB*64*256];           // conv outputs, [ib][t][256ch]
__device__ __align__(16) u16 g_crh[NB*64*128];         // cap_red split hi, [b][t][c]
__device__ __align__(16) u16 g_crl[NB*64*128];
__device__ __align__(16) u16 g_xh[(size_t)NI*NB*64*128];  // x split hi, [ib][t][c]
__device__ __align__(16) u16 g_xl[(size_t)NI*NB*64*128];
__device__ float  g_y[(size_t)NI*NB*1024];             // max-pooled pre-norm

// ---------------- stage 1: image prep (mean, norm, hypernet base) ----------------
__global__ __launch_bounds__(256) void k_img_prep(const float* __restrict__ img_embed,
                                                  const float* __restrict__ W_ri,
                                                  const float* __restrict__ b_ri) {
    __shared__ float gsh[LL];
    __shared__ float red[256];
    int i = blockIdx.x, tid = threadIdx.x;
    float ssq = 0.f;
    for (int c = tid; c < LL; c += 256) {
        float s = 0.f;
        #pragma unroll
        for (int t = 0; t < 36; t++) s += img_embed[((size_t)i*36 + t)*LL + c];
        s *= (1.0f/36.0f);
        gsh[c] = s;
        g_img_global[i*LL + c] = s;
        ssq += s*s;
    }
    red[tid] = ssq; __syncthreads();
    for (int s = 128; s > 0; s >>= 1) { if (tid < s) red[tid] += red[tid+s]; __syncthreads(); }
    if (tid == 0) g_inorm[i] = sqrtf(red[0]);
    if (tid < RR) {
        int o = tid;
        float acc = b_ri[o];
        const float* w = W_ri + (size_t)o * LL;
        for (int c = 0; c < LL; c++) acc = fmaf(w[c], gsh[c], acc);
        g_img_vec[i*RR + o] = acc;
    }
}

// ---------------- stage 2: hypernet kernel gen + weight BN, 128 CTAs --------------
__global__ __launch_bounds__(256) void k_gen(const float* __restrict__ mk_W,
                                             const float* __restrict__ mk_b,
                                             const float* __restrict__ wn_g,
                                             const float* __restrict__ wn_b) {
    extern __shared__ float sm[];
    float* base = sm;          // 128
    float* kraw = sm + 128;    // 8192
    int bx = blockIdx.x, tid = threadIdx.x;
    int i = bx >> 2, j = (bx >> 1) & 1, half = bx & 1;
    {   // zero BN-stat accumulators (exactly one pass across the 128 blocks)
        int z = bx*256 + tid;
        if (z < 2*NI*512) g_stats[z] = 0.0;
    }
    if (tid < RR) base[tid] = g_img_vec[i*RR + tid];
    __syncthreads();
    int fbase = half*8192;
    for (int f = tid; f < 8192; f += 256) {
        float acc = mk_b[j*16384 + fbase + f];
        const float* w = mk_W + ((size_t)j*16384 + fbase + f)*128;
        #pragma unroll 4
        for (int c = 0; c < 128; c++) acc = fmaf(w[c], base[c], acc);
        kraw[f] = acc;
    }
    __syncthreads();
    if (tid < 64) {
        int o = half*64 + tid;
        int g = o >> 6, op = o & 63;
        const float* kr = kraw + tid*128;
        float s = 0.f, s2 = 0.f;
        for (int c = 0; c < 128; c++) { float v = kr[c]; s += v; s2 += v*v; }
        float m   = s * (1.f/128.f);
        float var = s2 * (1.f/128.f) - m*m;
        float a   = wn_g[j*RR+o] * rsqrtf(var + 1e-5f);
        float bbv = wn_b[j*RR+o] - a*m;
        float* dst = g_kernT + (size_t)(i*2+j)*16384;
        for (int cik = 0; cik < 128; cik++) {
            int ci = cik >> 1, k = cik & 1;
            dst[((g*2+k)*64 + op)*64 + ci] = fmaf(a, kr[cik], bbv);
        }
    }
}

// ---------------- stage 3: caption reduction (split-bf16 out) + ca_W transform -----
__global__ __launch_bounds__(256) void k_cap_red(const float* __restrict__ cap_embed,
                                                 const float* __restrict__ W_rt,
                                                 const float* __restrict__ b_rt,
                                                 const float* __restrict__ ca_W) {
    extern __shared__ float sm[];
    float* ce = sm;                      // [c 300][t 64]
    int b = blockIdx.x, tid = threadIdx.x;
    for (int u = b*256 + tid; u < 32768; u += NB*256) {
        int ci = u & 63, row = (u >> 6) & 63, gk = (u >> 12) & 3, j2 = u >> 14;
        int o = (gk >> 1)*64 + row, k = gk & 1;
        g_caT[j2*16384 + (gk*64 + row)*64 + ci] = ca_W[((j2*128 + o)*64 + ci)*2 + k];
    }
    for (int idx = tid; idx < 300*TT; idx += 256) {
        int c = idx >> 6, t = idx & 63;
        ce[idx] = cap_embed[(size_t)b*TT*300 + t*300 + c];
    }
    __syncthreads();
    for (int q = tid; q < RR*16; q += 256) {
        int o = q >> 4, tq = (q & 15) * 4;
        float a0 = 0.f, a1 = 0.f, a2 = 0.f, a3 = 0.f;
        const float* w = W_rt + o*300;
        for (int c = 0; c < 300; c++) {
            float wv = w[c];
            float4 x4 = *(const float4*)(ce + c*TT + tq);
            a0 = fmaf(wv, x4.x, a0); a1 = fmaf(wv, x4.y, a1);
            a2 = fmaf(wv, x4.z, a2); a3 = fmaf(wv, x4.w, a3);
        }
        float bo = b_rt[o];
        float vv[4] = {a0 + bo, a1 + bo, a2 + bo, a3 + bo};
        #pragma unroll
        for (int n = 0; n < 4; n++) {
            u16 h, l; bsplit(vv[n], h, l);
            g_crh[b*8192 + (tq + n)*128 + o] = h;
            g_crl[b*8192 + (tq + n)*128 + o] = l;
        }
    }
}

// ---------------- stage 4: grouped convs via mma.sync, g-split, 2 CTAs/SM ----------
// A: [k 2][128 rows: 64 px-o | 64 ax-o][64 ci], 144B stride, hi/lo
// B: [65 t rows][64 c of this group], 144B stride, hi/lo; k=1 offsets base by 1 row
#define CV_AH 0
#define CV_AL 36864
#define CV_BH 73728
#define CV_BL 83088
#define CV_SMEM_TOTAL 92448

template<int TOUT>
__global__ __launch_bounds__(256, 2) void k_conv_mma(int j) {
    extern __shared__ char smc[];
    int bg = blockIdx.x, i = blockIdx.y, g = blockIdx.z, tid = threadIdx.x;
    int wid = tid >> 5, lane = tid & 31, gq = lane >> 2, t4 = lane & 3;
    int warpM = wid >> 1, warpN = wid & 1;

    // A build for this group only
    const float* kt = g_kernT + (size_t)(i*2 + j)*16384 + g*8192;
    const float* ct = g_caT + (size_t)j*16384 + g*8192;
    for (int idx = tid; idx < 16384; idx += 256) {
        int ci = idx & 63, row = (idx >> 6) & 127, k01 = idx >> 13;
        float v = (row < 64) ? kt[(k01*64 + row)*64 + ci]
                             : ct[(k01*64 + (row - 64))*64 + ci];
        u16 h, l; bsplit(v, h, l);
        int off = (k01*128 + row)*144 + ci*2;
        *(u16*)(smc + CV_AH + off) = h;
        *(u16*)(smc + CV_AL + off) = l;
    }

    // initial B prefetch (bs = 0)
    uint4 ph[2], pl[2];
    {
        int b0 = bg*16;
        size_t ib0 = (size_t)i*NB + b0;
        const uint4* sh = (const uint4*)((j == 0) ? (g_crh + (size_t)b0*8192) : (g_xh + ib0*8192));
        const uint4* sl = (const uint4*)((j == 0) ? (g_crl + (size_t)b0*8192) : (g_xl + ib0*8192));
        #pragma unroll
        for (int r = 0; r < 2; r++) {
            int u = tid + r*256;
            int t = u >> 3, s = u & 7;
            ph[r] = sh[t*16 + g*8 + s];
            pl[r] = sl[t*16 + g*8 + s];
        }
    }

    float st_s[2][2], st_q[2][2];   // [ms][hq]
    #pragma unroll
    for (int ms = 0; ms < 2; ms++)
        #pragma unroll
        for (int hq = 0; hq < 2; hq++) { st_s[ms][hq] = 0.f; st_q[ms][hq] = 0.f; }

    for (int bs = 0; bs < 16; bs++) {
        size_t ib = (size_t)i*NB + bg*16 + bs;
        __syncthreads();   // previous MMA done reading B
        #pragma unroll
        for (int r = 0; r < 2; r++) {
            int u = tid + r*256;
            int t = u >> 3, s = u & 7;
            *(uint4*)(smc + CV_BH + t*144 + s*16) = ph[r];
            *(uint4*)(smc + CV_BL + t*144 + s*16) = pl[r];
        }
        if (tid < 9) {
            *(uint4*)(smc + CV_BH + 64*144 + tid*16) = make_uint4(0,0,0,0);
            *(uint4*)(smc + CV_BL + 64*144 + tid*16) = make_uint4(0,0,0,0);
        }
        __syncthreads();
        if (bs + 1 < 16) {   // prefetch next caption, overlapped with MMA below
            int b2 = bg*16 + bs + 1;
            size_t ib2 = (size_t)i*NB + b2;
            const uint4* sh = (const uint4*)((j == 0) ? (g_crh + (size_t)b2*8192) : (g_xh + ib2*8192));
            const uint4* sl = (const uint4*)((j == 0) ? (g_crl + (size_t)b2*8192) : (g_xl + ib2*8192));
            #pragma unroll
            for (int r = 0; r < 2; r++) {
                int u = tid + r*256;
                int t = u >> 3, s = u & 7;
                ph[r] = sh[t*16 + g*8 + s];
                pl[r] = sl[t*16 + g*8 + s];
            }
        }

        float C[2][4][4];
        #pragma unroll
        for (int ms = 0; ms < 2; ms++)
            #pragma unroll
            for (int ns = 0; ns < 4; ns++)
                #pragma unroll
                for (int q = 0; q < 4; q++) C[ms][ns][q] = 0.f;

        #pragma unroll
        for (int term = 0; term < 3; term++) {
            const char* Ab = smc + ((term == 1) ? CV_AL : CV_AH);
            const char* Bb = smc + ((term == 2) ? CV_BL : CV_BH);
            #pragma unroll
            for (int ks = 0; ks < 2; ks++) {
                const char* As = Ab + (ks*128 + warpM*32 + gq)*144;
                const char* Bs = Bb + (warpN*32 + gq + ks)*144;
                #pragma unroll
                for (int kc = 0; kc < 4; kc++) {
                    int kb = (kc*16 + t4*2)*2;
                    u32 A[2][4], B[4][2];
                    #pragma unroll
                    for (int ms = 0; ms < 2; ms++) {
                        const char* p = As + ms*16*144 + kb;
                        A[ms][0] = *(const u32*)(p);
                        A[ms][1] = *(const u32*)(p + 8*144);
                        A[ms][2] = *(const u32*)(p + 16);
                        A[ms][3] = *(const u32*)(p + 8*144 + 16);
                    }
                    #pragma unroll
                    for (int ns = 0; ns < 4; ns++) {
                        const char* p = Bs + ns*8*144 + kb;
                        B[ns][0] = *(const u32*)(p);
                        B[ns][1] = *(const u32*)(p + 16);
                    }
                    #pragma unroll
                    for (int ms = 0; ms < 2; ms++)
                        #pragma unroll
                        for (int ns = 0; ns < 4; ns++)
                            mma16816(C[ms][ns], A[ms], B[ns]);
                }
            }
        }

        // epilogue: store h [t][256] + accumulate BN stats
        float* hp = g_h + ib*16384;
        #pragma unroll
        for (int ms = 0; ms < 2; ms++) {
            int r0 = warpM*32 + ms*16 + gq;
            int r1 = r0 + 8;
            int chA = (r0 < 64) ? (g*64 + r0) : (128 + g*64 + r0 - 64);
            int chB = (r1 < 64) ? (g*64 + r1) : (128 + g*64 + r1 - 64);
            #pragma unroll
            for (int ns = 0; ns < 4; ns++) {
                int tg = warpN*32 + ns*8 + t4*2;
                if (tg < TOUT) {
                    float v0 = C[ms][ns][0], v2 = C[ms][ns][2];
                    hp[tg*256 + chA] = v0;
                    hp[tg*256 + chB] = v2;
                    st_s[ms][0] += v0; st_q[ms][0] += v0*v0;
                    st_s[ms][1] += v2; st_q[ms][1] += v2*v2;
                }
                if (tg + 1 < TOUT) {
                    float v1 = C[ms][ns][1], v3 = C[ms][ns][3];
                    hp[(tg+1)*256 + chA] = v1;
                    hp[(tg+1)*256 + chB] = v3;
                    st_s[ms][0] += v1; st_q[ms][0] += v1*v1;
                    st_s[ms][1] += v3; st_q[ms][1] += v3*v3;
                }
            }
        }
    }
    double* st = g_stats + ((size_t)j*NI + i)*512;
    #pragma unroll
    for (int ms = 0; ms < 2; ms++)
        #pragma unroll
        for (int hq = 0; hq < 2; hq++) {
            float s = st_s[ms][hq], q = st_q[ms][hq];
            s += __shfl_xor_sync(0xffffffffu, s, 1);
            s += __shfl_xor_sync(0xffffffffu, s, 2);
            q += __shfl_xor_sync(0xffffffffu, q, 1);
            q += __shfl_xor_sync(0xffffffffu, q, 2);
            if (t4 == 0) {
                int r = warpM*32 + ms*16 + gq + hq*8;
                int ch = (r < 64) ? (g*64 + r) : (128 + g*64 + r - 64);
                atomicAdd(st + ch*2,     (double)s);
                atomicAdd(st + ch*2 + 1, (double)q);
            }
        }
}

// ---------------- stage 5: BN+ReLU + c1 via mma.sync; emits split-bf16 x ----------
#define C1_WH 0
#define C1_WL 67584
#define C1_BH 135168
#define C1_BL 168960
#define C1_AB 202752
#define C1_SMEM_TOTAL 204800

template<int TOUT>
__global__ __launch_bounds__(256) void k_c1_mma(const float* __restrict__ bn_g,
                                                const float* __restrict__ bn_b,
                                                const float* __restrict__ c1_b,
                                                const float* __restrict__ c1_W, int j) {
    extern __shared__ char smc[];
    float* aa = (float*)(smc + C1_AB);
    float* bb = aa + 256;
    int bg = blockIdx.x, i = blockIdx.y, tid = threadIdx.x;
    int wid = tid >> 5, lane = tid & 31, g = lane >> 2, t4 = lane & 3;
    int warpM = wid >> 1, warpN = wid & 1;

    {
        double s  = g_stats[((size_t)j*NI + i)*512 + tid*2];
        double s2 = g_stats[((size_t)j*NI + i)*512 + tid*2 + 1];
        double n  = (double)(NB*TOUT);
        float m   = (float)(s / n);
        float var = (float)(s2 / n) - m*m;
        float a   = bn_g[j*256 + tid] * rsqrtf(var + 1e-5f);
        aa[tid] = a;
        bb[tid] = bn_b[j*256 + tid] - a*m;
    }
    const float* Wsrc = c1_W + (size_t)j*128*256;
    for (int idx = tid; idx < 32768; idx += 256) {
        int o = idx >> 8, ch = idx & 255;
        u16 h, l; bsplit(Wsrc[idx], h, l);
        *(u16*)(smc + C1_WH + o*528 + ch*2) = h;
        *(u16*)(smc + C1_WL + o*528 + ch*2) = l;
    }
    float cb[2][2];
    #pragma unroll
    for (int ms = 0; ms < 2; ms++)
        #pragma unroll
        for (int hq = 0; hq < 2; hq++)
            cb[ms][hq] = c1_b[j*128 + warpM*32 + ms*16 + g + hq*8];

    // initial h prefetch (bs = 0)
    float4 hreg[16];
    {
        const float4* h4 = (const float4*)(g_h + ((size_t)i*NB + bg*16)*16384);
        #pragma unroll
        for (int r = 0; r < 16; r++) hreg[r] = h4[tid + r*256];
    }

    for (int bs = 0; bs < 16; bs++) {
        int b = bg*16 + bs;
        size_t ib = (size_t)i*NB + b;
        __syncthreads();
        #pragma unroll
        for (int r = 0; r < 16; r++) {
            int idx4 = tid + r*256;
            int t = idx4 >> 6, c4 = (idx4 & 63) * 4;
            float4 hv = hreg[r];
            bool live = (t < TOUT);
            float v0 = live ? fmaxf(fmaf(aa[c4    ], hv.x, bb[c4    ]), 0.f) : 0.f;
            float v1 = live ? fmaxf(fmaf(aa[c4 + 1], hv.y, bb[c4 + 1]), 0.f) : 0.f;
            float v2 = live ? fmaxf(fmaf(aa[c4 + 2], hv.z, bb[c4 + 2]), 0.f) : 0.f;
            float v3 = live ? fmaxf(fmaf(aa[c4 + 3], hv.w, bb[c4 + 3]), 0.f) : 0.f;
            u16 h0,l0,h1,l1,h2,l2,h3,l3;
            bsplit(v0,h0,l0); bsplit(v1,h1,l1); bsplit(v2,h2,l2); bsplit(v3,h3,l3);
            *(u32*)(smc + C1_BH + t*528 + c4*2    ) = pk16(h0,h1);
            *(u32*)(smc + C1_BH + t*528 + c4*2 + 4) = pk16(h2,h3);
            *(u32*)(smc + C1_BL + t*528 + c4*2    ) = pk16(l0,l1);
            *(u32*)(smc + C1_BL + t*528 + c4*2 + 4) = pk16(l2,l3);
        }
        __syncthreads();
        if (bs + 1 < 16) {
            const float4* h4 = (const float4*)(g_h + (ib + 1)*16384);
            #pragma unroll
            for (int r = 0; r < 16; r++) hreg[r] = h4[tid + r*256];
        }

        float C[2][4][4];
        #pragma unroll
        for (int ms = 0; ms < 2; ms++)
            #pragma unroll
            for (int ns = 0; ns < 4; ns++)
                #pragma unroll
                for (int q = 0; q < 4; q++) C[ms][ns][q] = 0.f;

        #pragma unroll
        for (int term = 0; term < 3; term++) {
            const char* As = smc + ((term == 1) ? C1_WL : C1_WH) + (warpM*32 + g)*528;
            const char* Bs = smc + ((term == 2) ? C1_BL : C1_BH) + (warpN*32 + g)*528;
            #pragma unroll
            for (int kc = 0; kc < 16; kc++) {
                int kb = (kc*16 + t4*2) * 2;
                u32 A[2][4], B[4][2];
                #pragma unroll
                for (int ms = 0; ms < 2; ms++) {
                    const char* p = As + ms*16*528 + kb;
                    A[ms][0] = *(const u32*)(p);
                    A[ms][1] = *(const u32*)(p + 8*528);
                    A[ms][2] = *(const u32*)(p + 16);
                    A[ms][3] = *(const u32*)(p + 8*528 + 16);
                }
                #pragma unroll
                for (int ns = 0; ns < 4; ns++) {
                    const char* p = Bs + ns*8*528 + kb;
                    B[ns][0] = *(const u32*)(p);
                    B[ns][1] = *(const u32*)(p + 16);
                }
                #pragma unroll
                for (int ms = 0; ms < 2; ms++)
                    #pragma unroll
                    for (int ns = 0; ns < 4; ns++)
                        mma16816(C[ms][ns], A[ms], B[ns]);
            }
        }

        u16* xh = g_xh + ib*8192;
        u16* xl = g_xl + ib*8192;
        #pragma unroll
        for (int ms = 0; ms < 2; ms++) {
            int row0 = warpM*32 + ms*16 + g;
            #pragma unroll
            for (int ns = 0; ns < 4; ns++) {
                int tg = warpN*32 + ns*8 + t4*2;
                #pragma unroll
                for (int dt = 0; dt < 2; dt++) {
                    int t = tg + dt;
                    float vA = (t < TOUT) ? (C[ms][ns][dt]     + cb[ms][0]) : 0.f;
                    float vB = (t < TOUT) ? (C[ms][ns][dt + 2] + cb[ms][1]) : 0.f;
                    u16 h, l;
                    bsplit(vA, h, l);
                    xh[t*128 + row0]     = h; xl[t*128 + row0]     = l;
                    bsplit(vB, h, l);
                    xh[t*128 + row0 + 8] = h; xl[t*128 + row0 + 8] = l;
                }
            }
        }
    }
}

// ---------------- stage 6: W_fc GEMM via mma.sync bf16 (split) + max-over-t -------
#define FC_WH 0
#define FC_WL 34816
#define FC_XH 69632
#define FC_XL 87040
#define FC_RED 104448
#define FC_SMEM_TOTAL 105472

__global__ __launch_bounds__(256, 2) void k_fc_mma(const float* __restrict__ W_fc,
                                                   const float* __restrict__ b_fc) {
    extern __shared__ char smc[];
    int lt = blockIdx.x, bg = blockIdx.y, i = blockIdx.z;
    int tid = threadIdx.x, wid = tid >> 5, lane = tid & 31;
    int g = lane >> 2, t4 = lane & 3;
    int warpM = wid >> 1, warpN = wid & 1;

    const float* Wsrc = W_fc + (size_t)lt*128*128;
    for (int idx = tid; idx < 16384; idx += 256) {
        int m = idx >> 7, c = idx & 127;
        u16 h, l; bsplit(Wsrc[idx], h, l);
        *(u16*)(smc + FC_WH + m*272 + c*2) = h;
        *(u16*)(smc + FC_WL + m*272 + c*2) = l;
    }
    float bfc = (tid < 128) ? b_fc[lt*128 + tid] : 0.f;
    float* redbuf = (float*)(smc + FC_RED);   // [2][128]

    const char* Abase = smc + (warpM*32 + g)*272;
    const char* Bbase = smc + (warpN*32 + g)*272;

    // initial X prefetch (bs = 0)
    uint4 px[8];
    {
        size_t ib0 = (size_t)i*NB + bg*16;
        const uint4* sh = (const uint4*)(g_xh + ib0*8192);
        const uint4* sl = (const uint4*)(g_xl + ib0*8192);
        #pragma unroll
        for (int r = 0; r < 4; r++) { px[r] = sh[tid + r*256]; px[4 + r] = sl[tid + r*256]; }
    }

    for (int bs = 0; bs < 16; bs++) {
        size_t ib = (size_t)i*NB + bg*16 + bs;
        __syncthreads();
        #pragma unroll
        for (int r = 0; r < 4; r++) {
            int u = tid + r*256;
            int t = u >> 4, sgm = u & 15;
            *(uint4*)(smc + FC_XH + t*272 + sgm*16) = px[r];
            *(uint4*)(smc + FC_XL + t*272 + sgm*16) = px[4 + r];
        }
        __syncthreads();
        if (bs + 1 < 16) {
            const uint4* sh = (const uint4*)(g_xh + (ib + 1)*8192);
            const uint4* sl = (const uint4*)(g_xl + (ib + 1)*8192);
            #pragma unroll
            for (int r = 0; r < 4; r++) { px[r] = sh[tid + r*256]; px[4 + r] = sl[tid + r*256]; }
        }

        float C[2][4][4];
        #pragma unroll
        for (int ms = 0; ms < 2; ms++)
            #pragma unroll
            for (int ns = 0; ns < 4; ns++)
                #pragma unroll
                for (int q = 0; q < 4; q++) C[ms][ns][q] = 0.f;

        #pragma unroll
        for (int term = 0; term < 3; term++) {
            const char* As = Abase + ((term == 1) ? FC_WL : FC_WH);
            const char* Bs = Bbase + ((term == 2) ? (FC_XL - FC_WH) : (FC_XH - FC_WH));
            #pragma unroll
            for (int kc = 0; kc < 8; kc++) {
                int kb = (kc*16 + t4*2) * 2;
                u32 A[2][4], B[4][2];
                #pragma unroll
                for (int ms = 0; ms < 2; ms++) {
                    const char* p = As + ms*16*272 + kb;
                    A[ms][0] = *(const u32*)(p);
                    A[ms][1] = *(const u32*)(p + 8*272);
                    A[ms][2] = *(const u32*)(p + 16);
                    A[ms][3] = *(const u32*)(p + 8*272 + 16);
                }
                #pragma unroll
                for (int ns = 0; ns < 4; ns++) {
                    const char* p = Bs + ns*8*272 + kb;
                    B[ns][0] = *(const u32*)(p);
                    B[ns][1] = *(const u32*)(p + 16);
                }
                #pragma unroll
                for (int ms = 0; ms < 2; ms++)
                    #pragma unroll
                    for (int ns = 0; ns < 4; ns++)
                        mma16816(C[ms][ns], A[ms], B[ns]);
            }
        }

        #pragma unroll
        for (int ms = 0; ms < 2; ms++) {
            float mA = -1e30f, mB = -1e30f;
            #pragma unroll
            for (int ns = 0; ns < 4; ns++) {
                int tg = warpN*32 + ns*8 + t4*2;
                if (tg < 62)     { mA = fmaxf(mA, C[ms][ns][0]); mB = fmaxf(mB, C[ms][ns][2]); }
                if (tg + 1 < 62) { mA = fmaxf(mA, C[ms][ns][1]); mB = fmaxf(mB, C[ms][ns][3]); }
            }
            mA = fmaxf(mA, __shfl_xor_sync(0xffffffffu, mA, 1));
            mA = fmaxf(mA, __shfl_xor_sync(0xffffffffu, mA, 2));
            mB = fmaxf(mB, __shfl_xor_sync(0xffffffffu, mB, 1));
            mB = fmaxf(mB, __shfl_xor_sync(0xffffffffu, mB, 2));
            if (t4 == 0) {
                int row = warpM*32 + ms*16 + g;
                redbuf[warpN*128 + row]     = mA;
                redbuf[warpN*128 + row + 8] = mB;
            }
        }
        __syncthreads();
        if (tid < 128) {
            float y = fmaxf(redbuf[tid], redbuf[128 + tid]) + bfc;
            g_y[ib*1024 + lt*128 + tid] = y;
        }
    }
}

// ---------------- stage 7: normalize + dot ----------------
__global__ __launch_bounds__(256) void k_final(float* __restrict__ out) {
    __shared__ float r1[256], r2[256];
    int b = blockIdx.x, i = blockIdx.y, tid = threadIdx.x;
    const float* y = g_y + (size_t)(i*NB + b)*1024;
    const float* g = g_img_global + i*LL;
    float d = 0.f, ss = 0.f;
    for (int l = tid; l < 1024; l += 256) { float yv = y[l]; d = fmaf(yv, g[l], d); ss = fmaf(yv, yv, ss); }
    r1[tid] = d; r2[tid] = ss; __syncthreads();
    for (int s = 128; s > 0; s >>= 1) {
        if (tid < s) { r1[tid] += r1[tid+s]; r2[tid] += r2[tid+s]; }
        __syncthreads();
    }
    if (tid == 0) out[i*NB + b] = r1[0] / (sqrtf(r2[0]) * g_inorm[i]);
}

// ---------------- launch ----------------
extern "C" void kernel_launch(void* const* d_in, const int* in_sizes, int n_in,
                              void* d_out, int out_size) {
    (void)in_sizes; (void)n_in; (void)out_size;
    const float* img_embed = (const float*)d_in[0];
    const float* cap_embed = (const float*)d_in[1];
    const float* W_ri = (const float*)d_in[2];
    const float* b_ri = (const float*)d_in[3];
    const float* W_rt = (const float*)d_in[4];
    const float* b_rt = (const float*)d_in[5];
    const float* mk_W = (const float*)d_in[6];
    const float* mk_b = (const float*)d_in[7];
    // d_in[8]=mbias_W, d_in[9]=mbias_b, d_in[13]=ca_b: exactly cancelled by training-mode BN
    const float* wn_g = (const float*)d_in[10];
    const float* wn_b = (const float*)d_in[11];
    const float* ca_W = (const float*)d_in[12];
    const float* bn_g = (const float*)d_in[14];
    const float* bn_b = (const float*)d_in[15];
    const float* c1_W = (const float*)d_in[16];
    const float* c1_b = (const float*)d_in[17];
    const float* W_fc = (const float*)d_in[18];
    const float* b_fc = (const float*)d_in[19];
    float* out = (float*)d_out;

    const int CAP_SMEM = 300*64*4;
    const int GEN_SMEM = (128 + 8192)*4;
    cudaFuncSetAttribute((const void*)k_cap_red,      cudaFuncAttributeMaxDynamicSharedMemorySize, CAP_SMEM);
    cudaFuncSetAttribute((const void*)k_gen,          cudaFuncAttributeMaxDynamicSharedMemorySize, GEN_SMEM);
    cudaFuncSetAttribute((const void*)k_conv_mma<63>, cudaFuncAttributeMaxDynamicSharedMemorySize, CV_SMEM_TOTAL);
    cudaFuncSetAttribute((const void*)k_conv_mma<62>, cudaFuncAttributeMaxDynamicSharedMemorySize, CV_SMEM_TOTAL);
    cudaFuncSetAttribute((const void*)k_c1_mma<63>,   cudaFuncAttributeMaxDynamicSharedMemorySize, C1_SMEM_TOTAL);
    cudaFuncSetAttribute((const void*)k_c1_mma<62>,   cudaFuncAttributeMaxDynamicSharedMemorySize, C1_SMEM_TOTAL);
    cudaFuncSetAttribute((const void*)k_fc_mma,       cudaFuncAttributeMaxDynamicSharedMemorySize, FC_SMEM_TOTAL);

    k_img_prep<<<NI, 256>>>(img_embed, W_ri, b_ri);
    k_gen<<<NI*2*2, 256, GEN_SMEM>>>(mk_W, mk_b, wn_g, wn_b);
    k_cap_red<<<NB, 256, CAP_SMEM>>>(cap_embed, W_rt, b_rt, ca_W);

    // block j = 0 (T 64 -> 63)
    k_conv_mma<63><<<dim3(NB/16, NI, 2), 256, CV_SMEM_TOTAL>>>(0);
    k_c1_mma<63><<<dim3(NB/16, NI), 256, C1_SMEM_TOTAL>>>(bn_g, bn_b, c1_b, c1_W, 0);

    // block j = 1 (T 63 -> 62)
    k_conv_mma<62><<<dim3(NB/16, NI, 2), 256, CV_SMEM_TOTAL>>>(1);
    k_c1_mma<62><<<dim3(NB/16, NI), 256, C1_SMEM_TOTAL>>>(bn_g, bn_b, c1_b, c1_W, 1);

    // tensor-core W_fc + max (16 captions/CTA), then normalize + dot
    k_fc_mma<<<dim3(8, NB/16, NI), 256, FC_SMEM_TOTAL>>>(W_fc, b_fc);
    k_final<<<dim3(NB, NI), 256>>>(out);
}

// round 10
// speedup vs baseline: 2.4503x; 1.0154x over previous
#include <cuda_runtime.h>
#include <cuda_bf16.h>
#include <math.h>

#define NI 32     // images
#define NB 128    // captions
#define RR 128    // reduced channels
#define LL 1024   // latent
#define TT 64     // initial time

typedef unsigned long long u64;
typedef unsigned int u32;
typedef unsigned short u16;

// ---------------- warp mma.sync bf16 + ldmatrix (sm_75/80 baseline PTX) -------
__device__ __forceinline__ void mma16816(float c[4], const u32 a[4], const u32 b[2]) {
    asm volatile("mma.sync.aligned.m16n8k16.row.col.f32.bf16.bf16.f32 "
                 "{%0,%1,%2,%3}, {%4,%5,%6,%7}, {%8,%9}, {%0,%1,%2,%3};"
                 : "+f"(c[0]), "+f"(c[1]), "+f"(c[2]), "+f"(c[3])
                 : "r"(a[0]), "r"(a[1]), "r"(a[2]), "r"(a[3]), "r"(b[0]), "r"(b[1]));
}
__device__ __forceinline__ void ldsm_x4(u32& r0, u32& r1, u32& r2, u32& r3, u32 addr) {
    asm volatile("ldmatrix.sync.aligned.m8n8.x4.shared.b16 {%0,%1,%2,%3}, [%4];"
                 : "=r"(r0), "=r"(r1), "=r"(r2), "=r"(r3) : "r"(addr));
}
__device__ __forceinline__ void bsplit(float v, u16& h, u16& l) {
    __nv_bfloat16 hb = __float2bfloat16(v);
    __nv_bfloat16 lb = __float2bfloat16(v - __bfloat162float(hb));
    h = __bfloat16_as_ushort(hb); l = __bfloat16_as_ushort(lb);
}
__device__ __forceinline__ u32 pk16(u16 a, u16 b) { return (u32)a | ((u32)b << 16); }

// ---------------- device scratch (static globals; no allocation) ----------------
__device__ float  g_img_global[NI*LL];
__device__ float  g_inorm[NI];
__device__ float  g_img_vec[NI*RR];
__device__ float  g_kernT[NI*2*4*64*64];               // [(i2j)][g*2+k][o'][ci]
__device__ float  g_caT[2*4*64*64];                    // [j][g*2+k][row][ci]
__device__ double g_stats[2*NI*512];                   // per-j per-image per-channel sum/sumsq
__device__ float  g_h[(size_t)NI*NB*64*256];           // conv outputs, [ib][t][256ch]
__device__ __align__(16) u16 g_crh[NB*64*128];         // cap_red split hi, [b][t][c]
__device__ __align__(16) u16 g_crl[NB*64*128];
__device__ __align__(16) u16 g_xh[(size_t)NI*NB*64*128];  // x split hi, [ib][t][c]
__device__ __align__(16) u16 g_xl[(size_t)NI*NB*64*128];
__device__ float  g_y[(size_t)NI*NB*1024];             // max-pooled pre-norm

// ---------------- stage 1: image prep (mean, norm, hypernet base) ----------------
__global__ __launch_bounds__(256) void k_img_prep(const float* __restrict__ img_embed,
                                                  const float* __restrict__ W_ri,
                                                  const float* __restrict__ b_ri) {
    __shared__ float gsh[LL];
    __shared__ float red[256];
    int i = blockIdx.x, tid = threadIdx.x;
    float ssq = 0.f;
    for (int c = tid; c < LL; c += 256) {
        float s = 0.f;
        #pragma unroll
        for (int t = 0; t < 36; t++) s += img_embed[((size_t)i*36 + t)*LL + c];
        s *= (1.0f/36.0f);
        gsh[c] = s;
        g_img_global[i*LL + c] = s;
        ssq += s*s;
    }
    red[tid] = ssq; __syncthreads();
    for (int s = 128; s > 0; s >>= 1) { if (tid < s) red[tid] += red[tid+s]; __syncthreads(); }
    if (tid == 0) g_inorm[i] = sqrtf(red[0]);
    if (tid < RR) {
        int o = tid;
        float acc = b_ri[o];
        const float* w = W_ri + (size_t)o * LL;
        for (int c = 0; c < LL; c++) acc = fmaf(w[c], gsh[c], acc);
        g_img_vec[i*RR + o] = acc;
    }
}

// ---------------- stage 2: hypernet kernel gen + weight BN, 128 CTAs --------------
__global__ __launch_bounds__(256) void k_gen(const float* __restrict__ mk_W,
                                             const float* __restrict__ mk_b,
                                             const float* __restrict__ wn_g,
                                             const float* __restrict__ wn_b) {
    extern __shared__ float sm[];
    float* base = sm;          // 128
    float* kraw = sm + 128;    // 8192
    int bx = blockIdx.x, tid = threadIdx.x;
    int i = bx >> 2, j = (bx >> 1) & 1, half = bx & 1;
    {
        int z = bx*256 + tid;
        if (z < 2*NI*512) g_stats[z] = 0.0;
    }
    if (tid < RR) base[tid] = g_img_vec[i*RR + tid];
    __syncthreads();
    int fbase = half*8192;
    for (int f = tid; f < 8192; f += 256) {
        float acc = mk_b[j*16384 + fbase + f];
        const float* w = mk_W + ((size_t)j*16384 + fbase + f)*128;
        #pragma unroll 4
        for (int c = 0; c < 128; c++) acc = fmaf(w[c], base[c], acc);
        kraw[f] = acc;
    }
    __syncthreads();
    if (tid < 64) {
        int o = half*64 + tid;
        int g = o >> 6, op = o & 63;
        const float* kr = kraw + tid*128;
        float s = 0.f, s2 = 0.f;
        for (int c = 0; c < 128; c++) { float v = kr[c]; s += v; s2 += v*v; }
        float m   = s * (1.f/128.f);
        float var = s2 * (1.f/128.f) - m*m;
        float a   = wn_g[j*RR+o] * rsqrtf(var + 1e-5f);
        float bbv = wn_b[j*RR+o] - a*m;
        float* dst = g_kernT + (size_t)(i*2+j)*16384;
        for (int cik = 0; cik < 128; cik++) {
            int ci = cik >> 1, k = cik & 1;
            dst[((g*2+k)*64 + op)*64 + ci] = fmaf(a, kr[cik], bbv);
        }
    }
}

// ---------------- stage 3: caption reduction (split-bf16 out) + ca_W transform -----
__global__ __launch_bounds__(256) void k_cap_red(const float* __restrict__ cap_embed,
                                                 const float* __restrict__ W_rt,
                                                 const float* __restrict__ b_rt,
                                                 const float* __restrict__ ca_W) {
    extern __shared__ float sm[];
    float* ce = sm;                      // [c 300][t 64]
    int b = blockIdx.x, tid = threadIdx.x;
    for (int u = b*256 + tid; u < 32768; u += NB*256) {
        int ci = u & 63, row = (u >> 6) & 63, gk = (u >> 12) & 3, j2 = u >> 14;
        int o = (gk >> 1)*64 + row, k = gk & 1;
        g_caT[j2*16384 + (gk*64 + row)*64 + ci] = ca_W[((j2*128 + o)*64 + ci)*2 + k];
    }
    for (int idx = tid; idx < 300*TT; idx += 256) {
        int c = idx >> 6, t = idx & 63;
        ce[idx] = cap_embed[(size_t)b*TT*300 + t*300 + c];
    }
    __syncthreads();
    for (int q = tid; q < RR*16; q += 256) {
        int o = q >> 4, tq = (q & 15) * 4;
        float a0 = 0.f, a1 = 0.f, a2 = 0.f, a3 = 0.f;
        const float* w = W_rt + o*300;
        for (int c = 0; c < 300; c++) {
            float wv = w[c];
            float4 x4 = *(const float4*)(ce + c*TT + tq);
            a0 = fmaf(wv, x4.x, a0); a1 = fmaf(wv, x4.y, a1);
            a2 = fmaf(wv, x4.z, a2); a3 = fmaf(wv, x4.w, a3);
        }
        float bo = b_rt[o];
        float vv[4] = {a0 + bo, a1 + bo, a2 + bo, a3 + bo};
        #pragma unroll
        for (int n = 0; n < 4; n++) {
            u16 h, l; bsplit(vv[n], h, l);
            g_crh[b*8192 + (tq + n)*128 + o] = h;
            g_crl[b*8192 + (tq + n)*128 + o] = l;
        }
    }
}

// ---------------- stage 4: grouped convs via mma.sync + ldmatrix, g-split ----------
// A: [k 2][128 rows: 64 px-o | 64 ax-o][64 ci], 144B stride, hi/lo
// B: [65 t rows][64 c of this group], 144B stride, hi/lo; k=1 offsets base by 1 row
#define CV_AH 0
#define CV_AL 36864
#define CV_BH 73728
#define CV_BL 83088
#define CV_SMEM_TOTAL 92448

template<int TOUT>
__global__ __launch_bounds__(256, 2) void k_conv_mma(int j) {
    extern __shared__ char smc[];
    u32 smb = (u32)__cvta_generic_to_shared(smc);
    int bg = blockIdx.x, i = blockIdx.y, g = blockIdx.z, tid = threadIdx.x;
    int wid = tid >> 5, lane = tid & 31, gq = lane >> 2, t4 = lane & 3;
    int warpM = wid >> 1, warpN = wid & 1;
    int mid = lane >> 3, rr8 = lane & 7;
    int aro = (mid & 1)*8 + rr8, akb = (mid >> 1)*16;
    int bro = (mid >> 1)*8 + rr8, bkb = (mid & 1)*16;

    // A build for this group only
    const float* kt = g_kernT + (size_t)(i*2 + j)*16384 + g*8192;
    const float* ct = g_caT + (size_t)j*16384 + g*8192;
    for (int idx = tid; idx < 16384; idx += 256) {
        int ci = idx & 63, row = (idx >> 6) & 127, k01 = idx >> 13;
        float v = (row < 64) ? kt[(k01*64 + row)*64 + ci]
                             : ct[(k01*64 + (row - 64))*64 + ci];
        u16 h, l; bsplit(v, h, l);
        int off = (k01*128 + row)*144 + ci*2;
        *(u16*)(smc + CV_AH + off) = h;
        *(u16*)(smc + CV_AL + off) = l;
    }

    // initial B prefetch (bs = 0)
    uint4 ph[2], pl[2];
    {
        int b0 = bg*16;
        size_t ib0 = (size_t)i*NB + b0;
        const uint4* sh = (const uint4*)((j == 0) ? (g_crh + (size_t)b0*8192) : (g_xh + ib0*8192));
        const uint4* sl = (const uint4*)((j == 0) ? (g_crl + (size_t)b0*8192) : (g_xl + ib0*8192));
        #pragma unroll
        for (int r = 0; r < 2; r++) {
            int u = tid + r*256;
            int t = u >> 3, s = u & 7;
            ph[r] = sh[t*16 + g*8 + s];
            pl[r] = sl[t*16 + g*8 + s];
        }
    }

    float st_s[2][2], st_q[2][2];   // [ms][hq]
    #pragma unroll
    for (int ms = 0; ms < 2; ms++)
        #pragma unroll
        for (int hq = 0; hq < 2; hq++) { st_s[ms][hq] = 0.f; st_q[ms][hq] = 0.f; }

    for (int bs = 0; bs < 16; bs++) {
        size_t ib = (size_t)i*NB + bg*16 + bs;
        __syncthreads();
        #pragma unroll
        for (int r = 0; r < 2; r++) {
            int u = tid + r*256;
            int t = u >> 3, s = u & 7;
            *(uint4*)(smc + CV_BH + t*144 + s*16) = ph[r];
            *(uint4*)(smc + CV_BL + t*144 + s*16) = pl[r];
        }
        if (tid < 9) {
            *(uint4*)(smc + CV_BH + 64*144 + tid*16) = make_uint4(0,0,0,0);
            *(uint4*)(smc + CV_BL + 64*144 + tid*16) = make_uint4(0,0,0,0);
        }
        __syncthreads();
        if (bs + 1 < 16) {
            int b2 = bg*16 + bs + 1;
            size_t ib2 = (size_t)i*NB + b2;
            const uint4* sh = (const uint4*)((j == 0) ? (g_crh + (size_t)b2*8192) : (g_xh + ib2*8192));
            const uint4* sl = (const uint4*)((j == 0) ? (g_crl + (size_t)b2*8192) : (g_xl + ib2*8192));
            #pragma unroll
            for (int r = 0; r < 2; r++) {
                int u = tid + r*256;
                int t = u >> 3, s = u & 7;
                ph[r] = sh[t*16 + g*8 + s];
                pl[r] = sl[t*16 + g*8 + s];
            }
        }

        float C[2][4][4];
        #pragma unroll
        for (int ms = 0; ms < 2; ms++)
            #pragma unroll
            for (int ns = 0; ns < 4; ns++)
                #pragma unroll
                for (int q = 0; q < 4; q++) C[ms][ns][q] = 0.f;

        #pragma unroll
        for (int term = 0; term < 3; term++) {
            u32 Ab = smb + ((term == 1) ? CV_AL : CV_AH);
            u32 Bb = smb + ((term == 2) ? CV_BL : CV_BH);
            #pragma unroll
            for (int ks = 0; ks < 2; ks++) {
                u32 aAddr = Ab + (u32)((ks*128 + warpM*32 + aro)*144 + akb);
                u32 bAddr = Bb + (u32)((warpN*32 + ks + bro)*144 + bkb);
                #pragma unroll
                for (int kc = 0; kc < 4; kc++) {
                    u32 A[2][4], B[4][2];
                    ldsm_x4(A[0][0], A[0][1], A[0][2], A[0][3], aAddr + kc*32);
                    ldsm_x4(A[1][0], A[1][1], A[1][2], A[1][3], aAddr + 16*144 + kc*32);
                    ldsm_x4(B[0][0], B[0][1], B[1][0], B[1][1], bAddr + kc*32);
                    ldsm_x4(B[2][0], B[2][1], B[3][0], B[3][1], bAddr + 16*144 + kc*32);
                    #pragma unroll
                    for (int ms = 0; ms < 2; ms++)
                        #pragma unroll
                        for (int ns = 0; ns < 4; ns++)
                            mma16816(C[ms][ns], A[ms], B[ns]);
                }
            }
        }

        // epilogue: store h [t][256] + accumulate BN stats
        float* hp = g_h + ib*16384;
        #pragma unroll
        for (int ms = 0; ms < 2; ms++) {
            int r0 = warpM*32 + ms*16 + gq;
            int r1 = r0 + 8;
            int chA = (r0 < 64) ? (g*64 + r0) : (128 + g*64 + r0 - 64);
            int chB = (r1 < 64) ? (g*64 + r1) : (128 + g*64 + r1 - 64);
            #pragma unroll
            for (int ns = 0; ns < 4; ns++) {
                int tg = warpN*32 + ns*8 + t4*2;
                if (tg < TOUT) {
                    float v0 = C[ms][ns][0], v2 = C[ms][ns][2];
                    hp[tg*256 + chA] = v0;
                    hp[tg*256 + chB] = v2;
                    st_s[ms][0] += v0; st_q[ms][0] += v0*v0;
                    st_s[ms][1] += v2; st_q[ms][1] += v2*v2;
                }
                if (tg + 1 < TOUT) {
                    float v1 = C[ms][ns][1], v3 = C[ms][ns][3];
                    hp[(tg+1)*256 + chA] = v1;
                    hp[(tg+1)*256 + chB] = v3;
                    st_s[ms][0] += v1; st_q[ms][0] += v1*v1;
                    st_s[ms][1] += v3; st_q[ms][1] += v3*v3;
                }
            }
        }
    }
    double* st = g_stats + ((size_t)j*NI + i)*512;
    #pragma unroll
    for (int ms = 0; ms < 2; ms++)
        #pragma unroll
        for (int hq = 0; hq < 2; hq++) {
            float s = st_s[ms][hq], q = st_q[ms][hq];
            s += __shfl_xor_sync(0xffffffffu, s, 1);
            s += __shfl_xor_sync(0xffffffffu, s, 2);
            q += __shfl_xor_sync(0xffffffffu, q, 1);
            q += __shfl_xor_sync(0xffffffffu, q, 2);
            if (t4 == 0) {
                int r = warpM*32 + ms*16 + gq + hq*8;
                int ch = (r < 64) ? (g*64 + r) : (128 + g*64 + r - 64);
                atomicAdd(st + ch*2,     (double)s);
                atomicAdd(st + ch*2 + 1, (double)q);
            }
        }
}

// ---------------- stage 5: BN+ReLU + c1 via mma.sync + ldmatrix --------------------
#define C1_WH 0
#define C1_WL 67584
#define C1_BH 135168
#define C1_BL 168960
#define C1_AB 202752
#define C1_SMEM_TOTAL 204800

template<int TOUT>
__global__ __launch_bounds__(256) void k_c1_mma(const float* __restrict__ bn_g,
                                                const float* __restrict__ bn_b,
                                                const float* __restrict__ c1_b,
                                                const float* __restrict__ c1_W, int j) {
    extern __shared__ char smc[];
    u32 smb = (u32)__cvta_generic_to_shared(smc);
    float* aa = (float*)(smc + C1_AB);
    float* bb = aa + 256;
    int bg = blockIdx.x, i = blockIdx.y, tid = threadIdx.x;
    int wid = tid >> 5, lane = tid & 31, g = lane >> 2, t4 = lane & 3;
    int warpM = wid >> 1, warpN = wid & 1;
    int mid = lane >> 3, rr8 = lane & 7;
    int aro = (mid & 1)*8 + rr8, akb = (mid >> 1)*16;
    int bro = (mid >> 1)*8 + rr8, bkb = (mid & 1)*16;

    {
        double s  = g_stats[((size_t)j*NI + i)*512 + tid*2];
        double s2 = g_stats[((size_t)j*NI + i)*512 + tid*2 + 1];
        double n  = (double)(NB*TOUT);
        float m   = (float)(s / n);
        float var = (float)(s2 / n) - m*m;
        float a   = bn_g[j*256 + tid] * rsqrtf(var + 1e-5f);
        aa[tid] = a;
        bb[tid] = bn_b[j*256 + tid] - a*m;
    }
    const float* Wsrc = c1_W + (size_t)j*128*256;
    for (int idx = tid; idx < 32768; idx += 256) {
        int o = idx >> 8, ch = idx & 255;
        u16 h, l; bsplit(Wsrc[idx], h, l);
        *(u16*)(smc + C1_WH + o*528 + ch*2) = h;
        *(u16*)(smc + C1_WL + o*528 + ch*2) = l;
    }
    float cb[2][2];
    #pragma unroll
    for (int ms = 0; ms < 2; ms++)
        #pragma unroll
        for (int hq = 0; hq < 2; hq++)
            cb[ms][hq] = c1_b[j*128 + warpM*32 + ms*16 + g + hq*8];

    // initial h prefetch (bs = 0)
    float4 hreg[16];
    {
        const float4* h4 = (const float4*)(g_h + ((size_t)i*NB + bg*16)*16384);
        #pragma unroll
        for (int r = 0; r < 16; r++) hreg[r] = h4[tid + r*256];
    }

    for (int bs = 0; bs < 16; bs++) {
        int b = bg*16 + bs;
        size_t ib = (size_t)i*NB + b;
        __syncthreads();
        #pragma unroll
        for (int r = 0; r < 16; r++) {
            int idx4 = tid + r*256;
            int t = idx4 >> 6, c4 = (idx4 & 63) * 4;
            float4 hv = hreg[r];
            bool live = (t < TOUT);
            float v0 = live ? fmaxf(fmaf(aa[c4    ], hv.x, bb[c4    ]), 0.f) : 0.f;
            float v1 = live ? fmaxf(fmaf(aa[c4 + 1], hv.y, bb[c4 + 1]), 0.f) : 0.f;
            float v2 = live ? fmaxf(fmaf(aa[c4 + 2], hv.z, bb[c4 + 2]), 0.f) : 0.f;
            float v3 = live ? fmaxf(fmaf(aa[c4 + 3], hv.w, bb[c4 + 3]), 0.f) : 0.f;
            u16 h0,l0,h1,l1,h2,l2,h3,l3;
            bsplit(v0,h0,l0); bsplit(v1,h1,l1); bsplit(v2,h2,l2); bsplit(v3,h3,l3);
            *(u32*)(smc + C1_BH + t*528 + c4*2    ) = pk16(h0,h1);
            *(u32*)(smc + C1_BH + t*528 + c4*2 + 4) = pk16(h2,h3);
            *(u32*)(smc + C1_BL + t*528 + c4*2    ) = pk16(l0,l1);
            *(u32*)(smc + C1_BL + t*528 + c4*2 + 4) = pk16(l2,l3);
        }
        __syncthreads();
        if (bs + 1 < 16) {
            const float4* h4 = (const float4*)(g_h + (ib + 1)*16384);
            #pragma unroll
            for (int r = 0; r < 16; r++) hreg[r] = h4[tid + r*256];
        }

        float C[2][4][4];
        #pragma unroll
        for (int ms = 0; ms < 2; ms++)
            #pragma unroll
            for (int ns = 0; ns < 4; ns++)
                #pragma unroll
                for (int q = 0; q < 4; q++) C[ms][ns][q] = 0.f;

        #pragma unroll
        for (int term = 0; term < 3; term++) {
            u32 aAddr = smb + ((term == 1) ? C1_WL : C1_WH)
                            + (u32)((warpM*32 + aro)*528 + akb);
            u32 bAddr = smb + ((term == 2) ? C1_BL : C1_BH)
                            + (u32)((warpN*32 + bro)*528 + bkb);
            #pragma unroll
            for (int kc = 0; kc < 16; kc++) {
                u32 A[2][4], B[4][2];
                ldsm_x4(A[0][0], A[0][1], A[0][2], A[0][3], aAddr + kc*32);
                ldsm_x4(A[1][0], A[1][1], A[1][2], A[1][3], aAddr + 16*528 + kc*32);
                ldsm_x4(B[0][0], B[0][1], B[1][0], B[1][1], bAddr + kc*32);
                ldsm_x4(B[2][0], B[2][1], B[3][0], B[3][1], bAddr + 16*528 + kc*32);
                #pragma unroll
                for (int ms = 0; ms < 2; ms++)
                    #pragma unroll
                    for (int ns = 0; ns < 4; ns++)
                        mma16816(C[ms][ns], A[ms], B[ns]);
            }
        }

        u16* xh = g_xh + ib*8192;
        u16* xl = g_xl + ib*8192;
        #pragma unroll
        for (int ms = 0; ms < 2; ms++) {
            int row0 = warpM*32 + ms*16 + g;
            #pragma unroll
            for (int ns = 0; ns < 4; ns++) {
                int tg = warpN*32 + ns*8 + t4*2;
                #pragma unroll
                for (int dt = 0; dt < 2; dt++) {
                    int t = tg + dt;
                    float vA = (t < TOUT) ? (C[ms][ns][dt]     + cb[ms][0]) : 0.f;
                    float vB = (t < TOUT) ? (C[ms][ns][dt + 2] + cb[ms][1]) : 0.f;
                    u16 h, l;
                    bsplit(vA, h, l);
                    xh[t*128 + row0]     = h; xl[t*128 + row0]     = l;
                    bsplit(vB, h, l);
                    xh[t*128 + row0 + 8] = h; xl[t*128 + row0 + 8] = l;
                }
            }
        }
    }
}

// ---------------- stage 6: W_fc GEMM via mma.sync + ldmatrix + max-over-t ----------
#define FC_WH 0
#define FC_WL 34816
#define FC_XH 69632
#define FC_XL 87040
#define FC_RED 104448
#define FC_SMEM_TOTAL 105472

__global__ __launch_bounds__(256, 2) void k_fc_mma(const float* __restrict__ W_fc,
                                                   const float* __restrict__ b_fc) {
    extern __shared__ char smc[];
    u32 smb = (u32)__cvta_generic_to_shared(smc);
    int lt = blockIdx.x, bg = blockIdx.y, i = blockIdx.z;
    int tid = threadIdx.x, wid = tid >> 5, lane = tid & 31;
    int g = lane >> 2, t4 = lane & 3;
    int warpM = wid >> 1, warpN = wid & 1;
    int mid = lane >> 3, rr8 = lane & 7;
    int aro = (mid & 1)*8 + rr8, akb = (mid >> 1)*16;
    int bro = (mid >> 1)*8 + rr8, bkb = (mid & 1)*16;

    const float* Wsrc = W_fc + (size_t)lt*128*128;
    for (int idx = tid; idx < 16384; idx += 256) {
        int m = idx >> 7, c = idx & 127;
        u16 h, l; bsplit(Wsrc[idx], h, l);
        *(u16*)(smc + FC_WH + m*272 + c*2) = h;
        *(u16*)(smc + FC_WL + m*272 + c*2) = l;
    }
    float bfc = (tid < 128) ? b_fc[lt*128 + tid] : 0.f;
    float* redbuf = (float*)(smc + FC_RED);   // [2][128]

    // initial X prefetch (bs = 0)
    uint4 px[8];
    {
        size_t ib0 = (size_t)i*NB + bg*16;
        const uint4* sh = (const uint4*)(g_xh + ib0*8192);
        const uint4* sl = (const uint4*)(g_xl + ib0*8192);
        #pragma unroll
        for (int r = 0; r < 4; r++) { px[r] = sh[tid + r*256]; px[4 + r] = sl[tid + r*256]; }
    }

    for (int bs = 0; bs < 16; bs++) {
        size_t ib = (size_t)i*NB + bg*16 + bs;
        __syncthreads();
        #pragma unroll
        for (int r = 0; r < 4; r++) {
            int u = tid + r*256;
            int t = u >> 4, sgm = u & 15;
            *(uint4*)(smc + FC_XH + t*272 + sgm*16) = px[r];
            *(uint4*)(smc + FC_XL + t*272 + sgm*16) = px[4 + r];
        }
        __syncthreads();
        if (bs + 1 < 16) {
            const uint4* sh = (const uint4*)(g_xh + (ib + 1)*8192);
            const uint4* sl = (const uint4*)(g_xl + (ib + 1)*8192);
            #pragma unroll
            for (int r = 0; r < 4; r++) { px[r] = sh[tid + r*256]; px[4 + r] = sl[tid + r*256]; }
        }

        float C[2][4][4];
        #pragma unroll
        for (int ms = 0; ms < 2; ms++)
            #pragma unroll
            for (int ns = 0; ns < 4; ns++)
                #pragma unroll
                for (int q = 0; q < 4; q++) C[ms][ns][q] = 0.f;

        #pragma unroll
        for (int term = 0; term < 3; term++) {
            u32 aAddr = smb + ((term == 1) ? FC_WL : FC_WH)
                            + (u32)((warpM*32 + aro)*272 + akb);
            u32 bAddr = smb + ((term == 2) ? FC_XL : FC_XH)
                            + (u32)((warpN*32 + bro)*272 + bkb);
            #pragma unroll
            for (int kc = 0; kc < 8; kc++) {
                u32 A[2][4], B[4][2];
                ldsm_x4(A[0][0], A[0][1], A[0][2], A[0][3], aAddr + kc*32);
                ldsm_x4(A[1][0], A[1][1], A[1][2], A[1][3], aAddr + 16*272 + kc*32);
                ldsm_x4(B[0][0], B[0][1], B[1][0], B[1][1], bAddr + kc*32);
                ldsm_x4(B[2][0], B[2][1], B[3][0], B[3][1], bAddr + 16*272 + kc*32);
                #pragma unroll
                for (int ms = 0; ms < 2; ms++)
                    #pragma unroll
                    for (int ns = 0; ns < 4; ns++)
                        mma16816(C[ms][ns], A[ms], B[ns]);
            }
        }

        #pragma unroll
        for (int ms = 0; ms < 2; ms++) {
            float mA = -1e30f, mB = -1e30f;
            #pragma unroll
            for (int ns = 0; ns < 4; ns++) {
                int tg = warpN*32 + ns*8 + t4*2;
                if (tg < 62)     { mA = fmaxf(mA, C[ms][ns][0]); mB = fmaxf(mB, C[ms][ns][2]); }
                if (tg + 1 < 62) { mA = fmaxf(mA, C[ms][ns][1]); mB = fmaxf(mB, C[ms][ns][3]); }
            }
            mA = fmaxf(mA, __shfl_xor_sync(0xffffffffu, mA, 1));
            mA = fmaxf(mA, __shfl_xor_sync(0xffffffffu, mA, 2));
            mB = fmaxf(mB, __shfl_xor_sync(0xffffffffu, mB, 1));
            mB = fmaxf(mB, __shfl_xor_sync(0xffffffffu, mB, 2));
            if (t4 == 0) {
                int row = warpM*32 + ms*16 + g;
                redbuf[warpN*128 + row]     = mA;
                redbuf[warpN*128 + row + 8] = mB;
            }
        }
        __syncthreads();
        if (tid < 128) {
            float y = fmaxf(redbuf[tid], redbuf[128 + tid]) + bfc;
            g_y[ib*1024 + lt*128 + tid] = y;
        }
    }
}

// ---------------- stage 7: normalize + dot ----------------
__global__ __launch_bounds__(256) void k_final(float* __restrict__ out) {
    __shared__ float r1[256], r2[256];
    int b = blockIdx.x, i = blockIdx.y, tid = threadIdx.x;
    const float* y = g_y + (size_t)(i*NB + b)*1024;
    const float* g = g_img_global + i*LL;
    float d = 0.f, ss = 0.f;
    for (int l = tid; l < 1024; l += 256) { float yv = y[l]; d = fmaf(yv, g[l], d); ss = fmaf(yv, yv, ss); }
    r1[tid] = d; r2[tid] = ss; __syncthreads();
    for (int s = 128; s > 0; s >>= 1) {
        if (tid < s) { r1[tid] += r1[tid+s]; r2[tid] += r2[tid+s]; }
        __syncthreads();
    }
    if (tid == 0) out[i*NB + b] = r1[0] / (sqrtf(r2[0]) * g_inorm[i]);
}

// ---------------- launch ----------------
extern "C" void kernel_launch(void* const* d_in, const int* in_sizes, int n_in,
                              void* d_out, int out_size) {
    (void)in_sizes; (void)n_in; (void)out_size;
    const float* img_embed = (const float*)d_in[0];
    const float* cap_embed = (const float*)d_in[1];
    const float* W_ri = (const float*)d_in[2];
    const float* b_ri = (const float*)d_in[3];
    const float* W_rt = (const float*)d_in[4];
    const float* b_rt = (const float*)d_in[5];
    const float* mk_W = (const float*)d_in[6];
    const float* mk_b = (const float*)d_in[7];
    // d_in[8]=mbias_W, d_in[9]=mbias_b, d_in[13]=ca_b: exactly cancelled by training-mode BN
    const float* wn_g = (const float*)d_in[10];
    const float* wn_b = (const float*)d_in[11];
    const float* ca_W = (const float*)d_in[12];
    const float* bn_g = (const float*)d_in[14];
    const float* bn_b = (const float*)d_in[15];
    const float* c1_W = (const float*)d_in[16];
    const float* c1_b = (const float*)d_in[17];
    const float* W_fc = (const float*)d_in[18];
    const float* b_fc = (const float*)d_in[19];
    float* out = (float*)d_out;

    const int CAP_SMEM = 300*64*4;
    const int GEN_SMEM = (128 + 8192)*4;
    cudaFuncSetAttribute((const void*)k_cap_red,      cudaFuncAttributeMaxDynamicSharedMemorySize, CAP_SMEM);
    cudaFuncSetAttribute((const void*)k_gen,          cudaFuncAttributeMaxDynamicSharedMemorySize, GEN_SMEM);
    cudaFuncSetAttribute((const void*)k_conv_mma<63>, cudaFuncAttributeMaxDynamicSharedMemorySize, CV_SMEM_TOTAL);
    cudaFuncSetAttribute((const void*)k_conv_mma<62>, cudaFuncAttributeMaxDynamicSharedMemorySize, CV_SMEM_TOTAL);
    cudaFuncSetAttribute((const void*)k_c1_mma<63>,   cudaFuncAttributeMaxDynamicSharedMemorySize, C1_SMEM_TOTAL);
    cudaFuncSetAttribute((const void*)k_c1_mma<62>,   cudaFuncAttributeMaxDynamicSharedMemorySize, C1_SMEM_TOTAL);
    cudaFuncSetAttribute((const void*)k_fc_mma,       cudaFuncAttributeMaxDynamicSharedMemorySize, FC_SMEM_TOTAL);

    k_img_prep<<<NI, 256>>>(img_embed, W_ri, b_ri);
    k_gen<<<NI*2*2, 256, GEN_SMEM>>>(mk_W, mk_b, wn_g, wn_b);
    k_cap_red<<<NB, 256, CAP_SMEM>>>(cap_embed, W_rt, b_rt, ca_W);

    // block j = 0 (T 64 -> 63)
    k_conv_mma<63><<<dim3(NB/16, NI, 2), 256, CV_SMEM_TOTAL>>>(0);
    k_c1_mma<63><<<dim3(NB/16, NI), 256, C1_SMEM_TOTAL>>>(bn_g, bn_b, c1_b, c1_W, 0);

    // block j = 1 (T 63 -> 62)
    k_conv_mma<62><<<dim3(NB/16, NI, 2), 256, CV_SMEM_TOTAL>>>(1);
    k_c1_mma<62><<<dim3(NB/16, NI), 256, C1_SMEM_TOTAL>>>(bn_g, bn_b, c1_b, c1_W, 1);

    // tensor-core W_fc + max (16 captions/CTA), then normalize + dot
    k_fc_mma<<<dim3(8, NB/16, NI), 256, FC_SMEM_TOTAL>>>(W_fc, b_fc);
    k_final<<<dim3(NB, NI), 256>>>(out);
}